// round 12
// baseline (speedup 1.0000x reference)
#include <cuda_runtime.h>
#include <cuda_fp16.h>
#include <cstdint>
#include <math.h>

// Problem dims
#define B_  256
#define T_  25
#define D_  4096
#define H_  512
#define G_  2048   // 4*H
#define M_  6400   // B*T

// Scratch (static __device__ arrays: allocation-free per harness rules)
__device__ float g_zx[(size_t)M_ * G_];        // 52.4 MB
__device__ float g_h[2][B_ * H_];
__device__ float g_c[B_ * H_];
__device__ __half g_a[(size_t)M_ * D_];        // 52.4 MB  fp16 x
__device__ __half g_b[(size_t)G_ * D_];        // 16.8 MB  fp16 W^T [N][K]

typedef unsigned long long u64;

// ---------- scalar f32x2 helpers (LSTM path) ----------
__device__ __forceinline__ u64 ffma2(u64 a, u64 b, u64 c) {
    u64 d; asm("fma.rn.f32x2 %0, %1, %2, %3;" : "=l"(d) : "l"(a), "l"(b), "l"(c));
    return d;
}
__device__ __forceinline__ u64 dup2(float x) {
    u64 d; asm("mov.b64 %0, {%1, %1};" : "=l"(d) : "f"(x)); return d;
}
__device__ __forceinline__ float2 unpack2(u64 v) {
    float2 r; asm("mov.b64 {%0, %1}, %2;" : "=f"(r.x), "=f"(r.y) : "l"(v)); return r;
}

__device__ __forceinline__ uint32_t smem_u32(const void* p) {
    uint32_t a;
    asm("{ .reg .u64 t; cvta.to.shared.u64 t, %1; cvt.u32.u64 %0, t; }" : "=r"(a) : "l"(p));
    return a;
}

// ---------- sm_80-baseline tensor primitives (compute_103-safe) ----------
__device__ __forceinline__ void cp_async16(uint32_t saddr, const void* gaddr) {
    asm volatile("cp.async.cg.shared.global [%0], [%1], 16;" :: "r"(saddr), "l"(gaddr));
}
__device__ __forceinline__ void cp_commit() {
    asm volatile("cp.async.commit_group;" ::: "memory");
}
__device__ __forceinline__ void cp_wait1() {
    asm volatile("cp.async.wait_group 1;" ::: "memory");
}
__device__ __forceinline__ void ldsm4(uint32_t addr, uint32_t* r) {
    asm volatile("ldmatrix.sync.aligned.m8n8.x4.shared.b16 {%0,%1,%2,%3}, [%4];"
        : "=r"(r[0]), "=r"(r[1]), "=r"(r[2]), "=r"(r[3]) : "r"(addr));
}
// fp16 MMA, fp32 accumulate
__device__ __forceinline__ void mma16816(float* c, const uint32_t* a,
                                         uint32_t b0, uint32_t b1) {
    asm volatile("mma.sync.aligned.m16n8k16.row.col.f32.f16.f16.f32 "
        "{%0,%1,%2,%3}, {%4,%5,%6,%7}, {%8,%9}, {%0,%1,%2,%3};"
        : "+f"(c[0]), "+f"(c[1]), "+f"(c[2]), "+f"(c[3])
        : "r"(a[0]), "r"(a[1]), "r"(a[2]), "r"(a[3]), "r"(b0), "r"(b1));
}

// ============================================================================
// nop kernel: exactly ONE pad. Harness issues 2 internal launches first, so
// slots are harness(1,2) prep_a(3) prep_b(4) nop(5) gemm(6) -> ncu -s 5 -c 1
// captures gemm_zx_mma.
// ============================================================================
__global__ void nop_pad() {}

// ============================================================================
// prep_a: x (C=0 slice) -> g_a fp16
// ============================================================================
__global__ void __launch_bounds__(256) prep_a(const float* __restrict__ x) {
    size_t idx = (size_t)blockIdx.x * 256 + threadIdx.x;   // float4 index
    int m  = (int)(idx >> 10);        // D_/4 = 1024
    int kq = (int)(idx & 1023);
    const float4 v = *(const float4*)(x + ((size_t)(m / T_) * (2 * T_) + (m % T_)) * D_ + kq * 4);
    size_t o = (size_t)m * D_ + kq * 4;
    __half2 p;
    p.x = __float2half_rn(v.x); p.y = __float2half_rn(v.y);
    *(__half2*)(g_a + o) = p;
    p.x = __float2half_rn(v.z); p.y = __float2half_rn(v.w);
    *(__half2*)(g_a + o + 2) = p;
}

// ============================================================================
// prep_b: transpose W [D_, G_] f32 -> g_b [G_, D_] fp16
// ============================================================================
__global__ void __launch_bounds__(256) prep_b(const float* __restrict__ W) {
    __shared__ float tile[32][33];
    int tx = threadIdx.x, ty = threadIdx.y;
    int n0 = blockIdx.x * 32, k0 = blockIdx.y * 32;
    #pragma unroll
    for (int j = 0; j < 4; j++)
        tile[ty + j * 8][tx] = W[(size_t)(k0 + ty + j * 8) * G_ + n0 + tx];
    __syncthreads();
    #pragma unroll
    for (int j = 0; j < 4; j++) {
        int n = n0 + ty + j * 8;
        int k = k0 + tx;
        g_b[(size_t)n * D_ + k] = __float2half_rn(tile[tx][ty + j * 8]);
    }
}

// ============================================================================
// gemm_zx_mma: zx = A@B^T + bias   (A = fp16(x), B = fp16(W)^T)
// mma.sync.m16n8k16.f16, cp.async double-buffered pipeline.
// CTA 128x128, BK=64 (128B rows, SW128 xor swizzle), 8 warps (2M x 4N), warp 64x32.
// R10's measured-best config (1 CTA/SM; R11's 2-CTA variant was neutral/worse).
// ============================================================================
#define NCHUNK   (D_ / 64)    // 64
#define TILE_SZ  16384
#define STAGE_SZ 32768        // 2 tiles: A, B
#define GEMM_SMEM (2 * STAGE_SZ)   // 64KB

__device__ __forceinline__ uint32_t sw_addr(uint32_t base, int row, int kbyte) {
    int off = row * 128 + kbyte;
    return base + (off ^ ((off >> 3) & 0x70));
}

__global__ void __launch_bounds__(256, 1) gemm_zx_mma(const float* __restrict__ bias)
{
    extern __shared__ char sm[];
    const uint32_t sbase = smem_u32(sm);
    const int tid = threadIdx.x, wid = tid >> 5, lane = tid & 31;
    const int bn = blockIdx.x, bm = blockIdx.y;

    const __half* gsrc[2];
    gsrc[0] = g_a + (size_t)(bm * 128) * D_;
    gsrc[1] = g_b + (size_t)(bn * 128) * D_;

    int lrow[4], lcol[4];
    uint32_t ssw[4];
    #pragma unroll
    for (int i = 0; i < 4; i++) {
        int q = i * 256 + tid;
        int row = q >> 3, c = q & 7;
        lrow[i] = row; lcol[i] = c * 8;
        int off = row * 128 + c * 16;
        ssw[i] = off ^ ((off >> 3) & 0x70);
    }

    auto issue_stage = [&](int s) {
        const int koff = s * 64;
        const uint32_t stg = sbase + (s & 1) * STAGE_SZ;
        #pragma unroll
        for (int tmat = 0; tmat < 2; tmat++) {
            const __half* gp = gsrc[tmat] + koff;
            uint32_t sp = stg + tmat * TILE_SZ;
            #pragma unroll
            for (int i = 0; i < 4; i++)
                cp_async16(sp + ssw[i], gp + (size_t)lrow[i] * D_ + lcol[i]);
        }
        cp_commit();
    };

    issue_stage(0);
    issue_stage(1);

    const int wm = (wid >> 2) * 64;   // warp M offset
    const int wn = (wid & 3) * 32;    // warp N offset
    const int lr = lane & 15, khalf = (lane >> 4) * 16;

    float acc[4][4][4];
    #pragma unroll
    for (int a = 0; a < 4; a++)
        #pragma unroll
        for (int b = 0; b < 4; b++)
            #pragma unroll
            for (int r = 0; r < 4; r++) acc[a][b][r] = 0.f;

    for (int c = 0; c < NCHUNK; c++) {
        cp_wait1();
        __syncthreads();
        const uint32_t stg = sbase + (c & 1) * STAGE_SZ;
        const uint32_t sA = stg, sB = stg + TILE_SZ;

        #pragma unroll
        for (int kb = 0; kb < 4; kb++) {
            const int kby = kb * 32 + khalf;
            uint32_t af[4][4], bf[2][4];
            #pragma unroll
            for (int mf = 0; mf < 4; mf++)
                ldsm4(sw_addr(sA, wm + mf * 16 + lr, kby), af[mf]);
            #pragma unroll
            for (int nb = 0; nb < 2; nb++)
                ldsm4(sw_addr(sB, wn + nb * 16 + lr, kby), bf[nb]);
            #pragma unroll
            for (int mf = 0; mf < 4; mf++)
                #pragma unroll
                for (int nf = 0; nf < 4; nf++) {
                    int nb = nf >> 1, sel = nf & 1;
                    mma16816(acc[mf][nf], af[mf], bf[nb][sel], bf[nb][sel + 2]);
                }
        }
        __syncthreads();
        if (c + 2 < NCHUNK) issue_stage(c + 2);
        else cp_commit();    // empty group keeps wait_group(1) invariant
    }

    // Epilogue: acc frag -> g_zx with bias
    const int g = lane >> 2, tg = lane & 3;
    #pragma unroll
    for (int mf = 0; mf < 4; mf++) {
        #pragma unroll
        for (int nf = 0; nf < 4; nf++) {
            int m0 = bm * 128 + wm + mf * 16 + g;
            int n0 = bn * 128 + wn + nf * 8 + tg * 2;
            float2 b2 = *(const float2*)&bias[n0];
            float2 v0 = make_float2(acc[mf][nf][0] + b2.x, acc[mf][nf][1] + b2.y);
            float2 v1 = make_float2(acc[mf][nf][2] + b2.x, acc[mf][nf][3] + b2.y);
            *(float2*)(g_zx + (size_t)m0 * G_ + n0)       = v0;
            *(float2*)(g_zx + (size_t)(m0 + 8) * G_ + n0) = v1;
        }
    }
}

// ============================================================================
// lstm_step: tile 32 batch x 64 gate-cols, 256 threads, grid 256 CTAs
// ============================================================================
#define LBK 16

__global__ void __launch_bounds__(256) lstm_step(const float* __restrict__ R, int t)
{
    __shared__ float As[LBK][32];
    __shared__ float Rs[LBK][64];
    __shared__ float zsm[32][64];

    int tid = threadIdx.x;
    int hb = blockIdx.x * 16;        // hidden-unit base (x4 gates = 64 cols)
    int b0 = blockIdx.y * 32;        // batch base

    const float* hprev = g_h[t & 1];
    float* hnext = g_h[(t + 1) & 1];

    int ty = tid >> 4;   // 0..15 -> row pair ty*2
    int tx = tid & 15;   // 0..15 -> cols tx*4

    u64 acc[4] = {0ull, 0ull, 0ull, 0ull};   // 1 row-pair x 4 cols

    if (t > 0) {
        int lr = tid & 31;                 // batch row
        int lk = (tid >> 5) << 1;          // k pair: 0,2,...,14
        const float* hp = hprev + (size_t)(b0 + lr) * H_ + lk;

        int rk = tid >> 4;                 // 0..15
        int rn = (tid & 15) << 2;          // 0..60
        int rgate = rn >> 4, rjj = rn & 15;
        const float* rp = R + (size_t)rk * G_ + rgate * H_ + hb + rjj;

        for (int k0 = 0; k0 < H_; k0 += LBK) {
            float2 a2 = *(const float2*)(hp + k0);
            As[lk + 0][lr] = a2.x;
            As[lk + 1][lr] = a2.y;
            *(float4*)&Rs[rk][rn] = *(const float4*)(rp + (size_t)k0 * G_);
            __syncthreads();

            #pragma unroll
            for (int k = 0; k < LBK; k++) {
                u64 a0 = *(const u64*)&As[k][ty * 2];
                float4 bv = *(const float4*)&Rs[k][tx * 4];
                acc[0] = ffma2(a0, dup2(bv.x), acc[0]);
                acc[1] = ffma2(a0, dup2(bv.y), acc[1]);
                acc[2] = ffma2(a0, dup2(bv.z), acc[2]);
                acc[3] = ffma2(a0, dup2(bv.w), acc[3]);
            }
            __syncthreads();
        }
    }

    // Stage recurrent contribution so each thread sees all 4 gates of a cell
    #pragma unroll
    for (int r = 0; r < 2; r++) {
        float o[4];
        #pragma unroll
        for (int j = 0; j < 4; j++) {
            float2 v = unpack2(acc[j]);
            o[j] = r ? v.y : v.x;
        }
        *(float4*)&zsm[ty * 2 + r][tx * 4] = make_float4(o[0], o[1], o[2], o[3]);
    }
    __syncthreads();

    // Pointwise: 512 (batch, hidden) cells, 2 per thread
    #pragma unroll
    for (int p = 0; p < 2; p++) {
        int lin = p * 256 + tid;
        int lb = lin >> 4;        // 0..31
        int jj = lin & 15;        // 0..15
        size_t zrow = (size_t)((b0 + lb) * T_ + t) * G_;
        int col = hb + jj;
        float zi = zsm[lb][jj]      + g_zx[zrow + col];
        float zf = zsm[lb][16 + jj] + g_zx[zrow + H_ + col];
        float zg = zsm[lb][32 + jj] + g_zx[zrow + 2 * H_ + col];
        float zo = zsm[lb][48 + jj] + g_zx[zrow + 3 * H_ + col];
        float ig = 1.0f / (1.0f + __expf(-zi));
        float fg = 1.0f / (1.0f + __expf(-zf));
        float gg = 2.0f / (1.0f + __expf(-2.0f * zg)) - 1.0f;
        float og = 1.0f / (1.0f + __expf(-zo));
        int ci = (b0 + lb) * H_ + hb + jj;
        float cp = (t == 0) ? 0.0f : g_c[ci];
        float cn = fg * cp + ig * gg;
        g_c[ci] = cn;
        hnext[ci] = og * (2.0f / (1.0f + __expf(-2.0f * cn)) - 1.0f);
    }
}

// ============================================================================
// head: y = leaky_relu(hT @ w1 + b1); out = softmax(y @ w2 + b2)
// ============================================================================
__global__ void __launch_bounds__(128) head_kernel(
    const float* __restrict__ w1, const float* __restrict__ b1,
    const float* __restrict__ w2, const float* __restrict__ b2,
    float* __restrict__ out)
{
    __shared__ float hs[H_];
    __shared__ float red0[4], red1[4];
    int b = blockIdx.x;
    int tid = threadIdx.x;

    const float* hrow = g_h[T_ & 1] + (size_t)b * H_;
    *(float4*)&hs[tid * 4] = *(const float4*)&hrow[tid * 4];
    __syncthreads();

    float a0 = 0.f, a1 = 0.f, a2 = 0.f, a3 = 0.f;
    #pragma unroll 4
    for (int k = 0; k < H_; k += 4) {
        a0 += hs[k]     * w1[(size_t)k * 128 + tid];
        a1 += hs[k + 1] * w1[(size_t)(k + 1) * 128 + tid];
        a2 += hs[k + 2] * w1[(size_t)(k + 2) * 128 + tid];
        a3 += hs[k + 3] * w1[(size_t)(k + 3) * 128 + tid];
    }
    float y = a0 + a1 + a2 + a3 + b1[tid];
    y = (y > 0.f) ? y : 0.2f * y;

    float p0 = y * w2[tid * 2];
    float p1 = y * w2[tid * 2 + 1];
    #pragma unroll
    for (int off = 16; off; off >>= 1) {
        p0 += __shfl_xor_sync(0xffffffffu, p0, off);
        p1 += __shfl_xor_sync(0xffffffffu, p1, off);
    }
    int w = tid >> 5;
    if ((tid & 31) == 0) { red0[w] = p0; red1[w] = p1; }
    __syncthreads();
    if (tid == 0) {
        float l0 = red0[0] + red0[1] + red0[2] + red0[3] + b2[0];
        float l1 = red1[0] + red1[1] + red1[2] + red1[3] + b2[1];
        float m = fmaxf(l0, l1);
        float e0 = expf(l0 - m), e1 = expf(l1 - m);
        float s = e0 + e1;
        out[b * 2]     = e0 / s;
        out[b * 2 + 1] = e1 / s;
    }
}

// ============================================================================
extern "C" void kernel_launch(void* const* d_in, const int* in_sizes, int n_in,
                              void* d_out, int out_size)
{
    const float* x    = (const float*)d_in[0];
    const float* W    = (const float*)d_in[1];
    const float* R    = (const float*)d_in[2];
    const float* bias = (const float*)d_in[3];
    const float* w1   = (const float*)d_in[4];
    const float* b1   = (const float*)d_in[5];
    const float* w2   = (const float*)d_in[6];
    const float* b2   = (const float*)d_in[7];
    float* out = (float*)d_out;

    static int configured = 0;
    if (!configured) {
        cudaFuncSetAttribute(gemm_zx_mma,
            cudaFuncAttributeMaxDynamicSharedMemorySize, GEMM_SMEM);
        configured = 1;
    }

    prep_a<<<(int)(((size_t)M_ * D_ / 4) / 256), 256>>>(x);
    prep_b<<<dim3(G_ / 32, D_ / 32), dim3(32, 8)>>>(W);
    nop_pad<<<1, 32>>>();          // single pad: gemm lands in ncu slot #6
    gemm_zx_mma<<<dim3(G_ / 128, M_ / 128), 256, GEMM_SMEM>>>(bias);
    for (int t = 0; t < T_; t++)
        lstm_step<<<dim3(H_ / 16, B_ / 32), 256>>>(R, t);
    head_kernel<<<B_, 128>>>(w1, b1, w2, b2, out);
}

// round 13
// speedup vs baseline: 1.5646x; 1.5646x over previous
#include <cuda_runtime.h>
#include <cuda_fp16.h>
#include <cstdint>
#include <math.h>

// Problem dims
#define B_  256
#define T_  25
#define D_  4096
#define H_  512
#define G_  2048   // 4*H
#define M_  6400   // B*T

// Scratch (static __device__ arrays: allocation-free per harness rules)
__device__ float g_zx[(size_t)M_ * G_];        // 52.4 MB
__device__ float g_zr[(size_t)B_ * G_];        // 2 MB   recurrent z per step
__device__ float g_h[B_ * H_];                 // fp32 h (for head)
__device__ float g_c[B_ * H_];
__device__ __half g_a[(size_t)M_ * D_];        // fp16 x
__device__ __half g_b[(size_t)G_ * D_];        // fp16 W^T [N][K]
__device__ __half g_R16[(size_t)G_ * H_];      // fp16 R^T [N=2048][K=512]
__device__ __half g_hhi[B_ * H_];              // fp16 hi(h)
__device__ __half g_hlo[B_ * H_];              // fp16 lo(h)

typedef unsigned long long u64;

__device__ __forceinline__ uint32_t smem_u32(const void* p) {
    uint32_t a;
    asm("{ .reg .u64 t; cvta.to.shared.u64 t, %1; cvt.u32.u64 %0, t; }" : "=r"(a) : "l"(p));
    return a;
}

// ---------- sm_80-baseline tensor primitives (compute_103-safe) ----------
__device__ __forceinline__ void cp_async16(uint32_t saddr, const void* gaddr) {
    asm volatile("cp.async.cg.shared.global [%0], [%1], 16;" :: "r"(saddr), "l"(gaddr));
}
__device__ __forceinline__ void cp_commit() {
    asm volatile("cp.async.commit_group;" ::: "memory");
}
__device__ __forceinline__ void cp_wait1() {
    asm volatile("cp.async.wait_group 1;" ::: "memory");
}
__device__ __forceinline__ void ldsm4(uint32_t addr, uint32_t* r) {
    asm volatile("ldmatrix.sync.aligned.m8n8.x4.shared.b16 {%0,%1,%2,%3}, [%4];"
        : "=r"(r[0]), "=r"(r[1]), "=r"(r[2]), "=r"(r[3]) : "r"(addr));
}
__device__ __forceinline__ void mma16816(float* c, const uint32_t* a,
                                         uint32_t b0, uint32_t b1) {
    asm volatile("mma.sync.aligned.m16n8k16.row.col.f32.f16.f16.f32 "
        "{%0,%1,%2,%3}, {%4,%5,%6,%7}, {%8,%9}, {%0,%1,%2,%3};"
        : "+f"(c[0]), "+f"(c[1]), "+f"(c[2]), "+f"(c[3])
        : "r"(a[0]), "r"(a[1]), "r"(a[2]), "r"(a[3]), "r"(b0), "r"(b1));
}

__device__ __forceinline__ void split_fp16(float v, __half& h, __half& l) {
    h = __float2half_rn(v);
    l = __float2half_rn(v - __half2float(h));
}

__device__ __forceinline__ uint32_t sw_addr(uint32_t base, int row, int kbyte) {
    int off = row * 128 + kbyte;
    return base + (off ^ ((off >> 3) & 0x70));
}

// ============================================================================
// prep_R: transpose R [H_, G_] f32 -> g_R16 [G_, H_] fp16
// ============================================================================
__global__ void __launch_bounds__(256) prep_R(const float* __restrict__ R) {
    __shared__ float tile[32][33];
    int tx = threadIdx.x, ty = threadIdx.y;
    int n0 = blockIdx.x * 32, k0 = blockIdx.y * 32;
    #pragma unroll
    for (int j = 0; j < 4; j++)
        tile[ty + j * 8][tx] = R[(size_t)(k0 + ty + j * 8) * G_ + n0 + tx];
    __syncthreads();
    #pragma unroll
    for (int j = 0; j < 4; j++) {
        int n = n0 + ty + j * 8;
        int k = k0 + tx;
        g_R16[(size_t)n * H_ + k] = __float2half_rn(tile[tx][ty + j * 8]);
    }
}

// ============================================================================
// prep_a: x (C=0 slice) -> g_a fp16
// ============================================================================
__global__ void __launch_bounds__(256) prep_a(const float* __restrict__ x) {
    size_t idx = (size_t)blockIdx.x * 256 + threadIdx.x;
    int m  = (int)(idx >> 10);
    int kq = (int)(idx & 1023);
    const float4 v = *(const float4*)(x + ((size_t)(m / T_) * (2 * T_) + (m % T_)) * D_ + kq * 4);
    size_t o = (size_t)m * D_ + kq * 4;
    __half2 p;
    p.x = __float2half_rn(v.x); p.y = __float2half_rn(v.y);
    *(__half2*)(g_a + o) = p;
    p.x = __float2half_rn(v.z); p.y = __float2half_rn(v.w);
    *(__half2*)(g_a + o + 2) = p;
}

// ============================================================================
// prep_b: transpose W [D_, G_] f32 -> g_b [G_, D_] fp16
// ============================================================================
__global__ void __launch_bounds__(256) prep_b(const float* __restrict__ W) {
    __shared__ float tile[32][33];
    int tx = threadIdx.x, ty = threadIdx.y;
    int n0 = blockIdx.x * 32, k0 = blockIdx.y * 32;
    #pragma unroll
    for (int j = 0; j < 4; j++)
        tile[ty + j * 8][tx] = W[(size_t)(k0 + ty + j * 8) * G_ + n0 + tx];
    __syncthreads();
    #pragma unroll
    for (int j = 0; j < 4; j++) {
        int n = n0 + ty + j * 8;
        int k = k0 + tx;
        g_b[(size_t)n * D_ + k] = __float2half_rn(tile[tx][ty + j * 8]);
    }
}

// ============================================================================
// gemm_zx_mma: zx = A@B^T + bias  (R10's measured-best config: 313us, tensor 56%)
// ============================================================================
#define NCHUNK   (D_ / 64)    // 64
#define TILE_SZ  16384
#define STAGE_SZ 32768
#define GEMM_SMEM (2 * STAGE_SZ)   // 64KB

__global__ void __launch_bounds__(256, 1) gemm_zx_mma(const float* __restrict__ bias)
{
    extern __shared__ char sm[];
    const uint32_t sbase = smem_u32(sm);
    const int tid = threadIdx.x, wid = tid >> 5, lane = tid & 31;
    const int bn = blockIdx.x, bm = blockIdx.y;

    const __half* gsrc[2];
    gsrc[0] = g_a + (size_t)(bm * 128) * D_;
    gsrc[1] = g_b + (size_t)(bn * 128) * D_;

    int lrow[4], lcol[4];
    uint32_t ssw[4];
    #pragma unroll
    for (int i = 0; i < 4; i++) {
        int q = i * 256 + tid;
        int row = q >> 3, c = q & 7;
        lrow[i] = row; lcol[i] = c * 8;
        int off = row * 128 + c * 16;
        ssw[i] = off ^ ((off >> 3) & 0x70);
    }

    auto issue_stage = [&](int s) {
        const int koff = s * 64;
        const uint32_t stg = sbase + (s & 1) * STAGE_SZ;
        #pragma unroll
        for (int tmat = 0; tmat < 2; tmat++) {
            const __half* gp = gsrc[tmat] + koff;
            uint32_t sp = stg + tmat * TILE_SZ;
            #pragma unroll
            for (int i = 0; i < 4; i++)
                cp_async16(sp + ssw[i], gp + (size_t)lrow[i] * D_ + lcol[i]);
        }
        cp_commit();
    };

    issue_stage(0);
    issue_stage(1);

    const int wm = (wid >> 2) * 64;
    const int wn = (wid & 3) * 32;
    const int lr = lane & 15, khalf = (lane >> 4) * 16;

    float acc[4][4][4];
    #pragma unroll
    for (int a = 0; a < 4; a++)
        #pragma unroll
        for (int b = 0; b < 4; b++)
            #pragma unroll
            for (int r = 0; r < 4; r++) acc[a][b][r] = 0.f;

    for (int c = 0; c < NCHUNK; c++) {
        cp_wait1();
        __syncthreads();
        const uint32_t stg = sbase + (c & 1) * STAGE_SZ;
        const uint32_t sA = stg, sB = stg + TILE_SZ;

        #pragma unroll
        for (int kb = 0; kb < 4; kb++) {
            const int kby = kb * 32 + khalf;
            uint32_t af[4][4], bf[2][4];
            #pragma unroll
            for (int mf = 0; mf < 4; mf++)
                ldsm4(sw_addr(sA, wm + mf * 16 + lr, kby), af[mf]);
            #pragma unroll
            for (int nb = 0; nb < 2; nb++)
                ldsm4(sw_addr(sB, wn + nb * 16 + lr, kby), bf[nb]);
            #pragma unroll
            for (int mf = 0; mf < 4; mf++)
                #pragma unroll
                for (int nf = 0; nf < 4; nf++) {
                    int nb = nf >> 1, sel = nf & 1;
                    mma16816(acc[mf][nf], af[mf], bf[nb][sel], bf[nb][sel + 2]);
                }
        }
        __syncthreads();
        if (c + 2 < NCHUNK) issue_stage(c + 2);
        else cp_commit();
    }

    const int g = lane >> 2, tg = lane & 3;
    #pragma unroll
    for (int mf = 0; mf < 4; mf++) {
        #pragma unroll
        for (int nf = 0; nf < 4; nf++) {
            int m0 = bm * 128 + wm + mf * 16 + g;
            int n0 = bn * 128 + wn + nf * 8 + tg * 2;
            float2 b2 = *(const float2*)&bias[n0];
            float2 v0 = make_float2(acc[mf][nf][0] + b2.x, acc[mf][nf][1] + b2.y);
            float2 v1 = make_float2(acc[mf][nf][2] + b2.x, acc[mf][nf][3] + b2.y);
            *(float2*)(g_zx + (size_t)m0 * G_ + n0)       = v0;
            *(float2*)(g_zx + (size_t)(m0 + 8) * G_ + n0) = v1;
        }
    }
}

// ============================================================================
// lstm_gemm: z_rec[256,2048] = h@R^T  (h = hhi+hlo fp16 split, R fp16)
// Same pipeline, K=512 (8 chunks), 3 tiles/stage, grid (16, 2) = 32 CTAs.
// ============================================================================
#define NCHUNK2  (H_ / 64)    // 8
#define STAGE2   (3 * TILE_SZ)           // 48KB
#define LG_SMEM  (2 * STAGE2)            // 96KB

__global__ void __launch_bounds__(256, 1) lstm_gemm()
{
    extern __shared__ char sm[];
    const uint32_t sbase = smem_u32(sm);
    const int tid = threadIdx.x, wid = tid >> 5, lane = tid & 31;
    const int bn = blockIdx.x, bm = blockIdx.y;

    const __half* gsrc[3];
    gsrc[0] = g_hhi + (size_t)(bm * 128) * H_;
    gsrc[1] = g_hlo + (size_t)(bm * 128) * H_;
    gsrc[2] = g_R16 + (size_t)(bn * 128) * H_;

    int lrow[4], lcol[4];
    uint32_t ssw[4];
    #pragma unroll
    for (int i = 0; i < 4; i++) {
        int q = i * 256 + tid;
        int row = q >> 3, c = q & 7;
        lrow[i] = row; lcol[i] = c * 8;
        int off = row * 128 + c * 16;
        ssw[i] = off ^ ((off >> 3) & 0x70);
    }

    auto issue_stage = [&](int s) {
        const int koff = s * 64;
        const uint32_t stg = sbase + (s & 1) * STAGE2;
        #pragma unroll
        for (int tmat = 0; tmat < 3; tmat++) {
            const __half* gp = gsrc[tmat] + koff;
            uint32_t sp = stg + tmat * TILE_SZ;
            #pragma unroll
            for (int i = 0; i < 4; i++)
                cp_async16(sp + ssw[i], gp + (size_t)lrow[i] * H_ + lcol[i]);
        }
        cp_commit();
    };

    issue_stage(0);
    issue_stage(1);

    const int wm = (wid >> 2) * 64;
    const int wn = (wid & 3) * 32;
    const int lr = lane & 15, khalf = (lane >> 4) * 16;

    float acc[4][4][4];
    #pragma unroll
    for (int a = 0; a < 4; a++)
        #pragma unroll
        for (int b = 0; b < 4; b++)
            #pragma unroll
            for (int r = 0; r < 4; r++) acc[a][b][r] = 0.f;

    for (int c = 0; c < NCHUNK2; c++) {
        cp_wait1();
        __syncthreads();
        const uint32_t stg = sbase + (c & 1) * STAGE2;
        const uint32_t sAh = stg, sAl = stg + TILE_SZ, sB = stg + 2 * TILE_SZ;

        #pragma unroll
        for (int kb = 0; kb < 4; kb++) {
            const int kby = kb * 32 + khalf;
            uint32_t ah[4][4], al[4][4], bf[2][4];
            #pragma unroll
            for (int mf = 0; mf < 4; mf++) {
                ldsm4(sw_addr(sAh, wm + mf * 16 + lr, kby), ah[mf]);
                ldsm4(sw_addr(sAl, wm + mf * 16 + lr, kby), al[mf]);
            }
            #pragma unroll
            for (int nb = 0; nb < 2; nb++)
                ldsm4(sw_addr(sB, wn + nb * 16 + lr, kby), bf[nb]);
            #pragma unroll
            for (int mf = 0; mf < 4; mf++)
                #pragma unroll
                for (int nf = 0; nf < 4; nf++) {
                    int nb = nf >> 1, sel = nf & 1;
                    mma16816(acc[mf][nf], ah[mf], bf[nb][sel], bf[nb][sel + 2]);
                    mma16816(acc[mf][nf], al[mf], bf[nb][sel], bf[nb][sel + 2]);
                }
        }
        __syncthreads();
        if (c + 2 < NCHUNK2) issue_stage(c + 2);
        else cp_commit();
    }

    const int g = lane >> 2, tg = lane & 3;
    #pragma unroll
    for (int mf = 0; mf < 4; mf++) {
        #pragma unroll
        for (int nf = 0; nf < 4; nf++) {
            int m0 = bm * 128 + wm + mf * 16 + g;
            int n0 = bn * 128 + wn + nf * 8 + tg * 2;
            float2 v0 = make_float2(acc[mf][nf][0], acc[mf][nf][1]);
            float2 v1 = make_float2(acc[mf][nf][2], acc[mf][nf][3]);
            *(float2*)(g_zr + (size_t)m0 * G_ + n0)       = v0;
            *(float2*)(g_zr + (size_t)(m0 + 8) * G_ + n0) = v1;
        }
    }
}

// ============================================================================
// gate_step: z = zx[:,t,:] (+ z_rec if t>0); gates; update c, h (fp32 + fp16 split)
// Grid 256 CTAs (one per batch row), 256 threads (2 hidden units each).
// ============================================================================
__global__ void __launch_bounds__(256) gate_step(int t)
{
    int b = blockIdx.x;
    int tid = threadIdx.x;
    size_t zxrow = (size_t)(b * T_ + t) * G_;
    size_t zrrow = (size_t)b * G_;

    #pragma unroll
    for (int p = 0; p < 2; p++) {
        int j = p * 256 + tid;
        float zi = g_zx[zxrow + j];
        float zf = g_zx[zxrow + H_ + j];
        float zg = g_zx[zxrow + 2 * H_ + j];
        float zo = g_zx[zxrow + 3 * H_ + j];
        float cp = 0.0f;
        if (t > 0) {
            zi += g_zr[zrrow + j];
            zf += g_zr[zrrow + H_ + j];
            zg += g_zr[zrrow + 2 * H_ + j];
            zo += g_zr[zrrow + 3 * H_ + j];
            cp = g_c[b * H_ + j];
        }
        float ig = 1.0f / (1.0f + __expf(-zi));
        float fg = 1.0f / (1.0f + __expf(-zf));
        float gg = 2.0f / (1.0f + __expf(-2.0f * zg)) - 1.0f;
        float og = 1.0f / (1.0f + __expf(-zo));
        float cn = fg * cp + ig * gg;
        float hn = og * (2.0f / (1.0f + __expf(-2.0f * cn)) - 1.0f);
        int ci = b * H_ + j;
        g_c[ci] = cn;
        g_h[ci] = hn;
        __half hh, hl;
        split_fp16(hn, hh, hl);
        g_hhi[ci] = hh;
        g_hlo[ci] = hl;
    }
}

// ============================================================================
// head: y = leaky_relu(hT @ w1 + b1); out = softmax(y @ w2 + b2)
// ============================================================================
__global__ void __launch_bounds__(128) head_kernel(
    const float* __restrict__ w1, const float* __restrict__ b1,
    const float* __restrict__ w2, const float* __restrict__ b2,
    float* __restrict__ out)
{
    __shared__ float hs[H_];
    __shared__ float red0[4], red1[4];
    int b = blockIdx.x;
    int tid = threadIdx.x;

    const float* hrow = g_h + (size_t)b * H_;
    *(float4*)&hs[tid * 4] = *(const float4*)&hrow[tid * 4];
    __syncthreads();

    float a0 = 0.f, a1 = 0.f, a2 = 0.f, a3 = 0.f;
    #pragma unroll 4
    for (int k = 0; k < H_; k += 4) {
        a0 += hs[k]     * w1[(size_t)k * 128 + tid];
        a1 += hs[k + 1] * w1[(size_t)(k + 1) * 128 + tid];
        a2 += hs[k + 2] * w1[(size_t)(k + 2) * 128 + tid];
        a3 += hs[k + 3] * w1[(size_t)(k + 3) * 128 + tid];
    }
    float y = a0 + a1 + a2 + a3 + b1[tid];
    y = (y > 0.f) ? y : 0.2f * y;

    float p0 = y * w2[tid * 2];
    float p1 = y * w2[tid * 2 + 1];
    #pragma unroll
    for (int off = 16; off; off >>= 1) {
        p0 += __shfl_xor_sync(0xffffffffu, p0, off);
        p1 += __shfl_xor_sync(0xffffffffu, p1, off);
    }
    int w = tid >> 5;
    if ((tid & 31) == 0) { red0[w] = p0; red1[w] = p1; }
    __syncthreads();
    if (tid == 0) {
        float l0 = red0[0] + red0[1] + red0[2] + red0[3] + b2[0];
        float l1 = red1[0] + red1[1] + red1[2] + red1[3] + b2[1];
        float m = fmaxf(l0, l1);
        float e0 = expf(l0 - m), e1 = expf(l1 - m);
        float s = e0 + e1;
        out[b * 2]     = e0 / s;
        out[b * 2 + 1] = e1 / s;
    }
}

// ============================================================================
extern "C" void kernel_launch(void* const* d_in, const int* in_sizes, int n_in,
                              void* d_out, int out_size)
{
    const float* x    = (const float*)d_in[0];
    const float* W    = (const float*)d_in[1];
    const float* R    = (const float*)d_in[2];
    const float* bias = (const float*)d_in[3];
    const float* w1   = (const float*)d_in[4];
    const float* b1   = (const float*)d_in[5];
    const float* w2   = (const float*)d_in[6];
    const float* b2   = (const float*)d_in[7];
    float* out = (float*)d_out;

    static int configured = 0;
    if (!configured) {
        cudaFuncSetAttribute(gemm_zx_mma,
            cudaFuncAttributeMaxDynamicSharedMemorySize, GEMM_SMEM);
        cudaFuncSetAttribute(lstm_gemm,
            cudaFuncAttributeMaxDynamicSharedMemorySize, LG_SMEM);
        configured = 1;
    }

    // slots: harness(1,2) prep_R(3) prep_a(4) prep_b(5) gemm_zx(6) -> ncu on gemm
    prep_R<<<dim3(G_ / 32, H_ / 32), dim3(32, 8)>>>(R);
    prep_a<<<(int)(((size_t)M_ * D_ / 4) / 256), 256>>>(x);
    prep_b<<<dim3(G_ / 32, D_ / 32), dim3(32, 8)>>>(W);
    gemm_zx_mma<<<dim3(G_ / 128, M_ / 128), 256, GEMM_SMEM>>>(bias);
    for (int t = 0; t < T_; t++) {
        if (t > 0)
            lstm_gemm<<<dim3(G_ / 128, B_ / 128), 256, LG_SMEM>>>();
        gate_step<<<B_, 256>>>(t);
    }
    head_kernel<<<B_, 128>>>(w1, b1, w2, b2, out);
}

// round 14
// speedup vs baseline: 1.8860x; 1.2055x over previous
#include <cuda_runtime.h>
#include <cuda_fp16.h>
#include <cstdint>
#include <math.h>

// Problem dims
#define B_  256
#define T_  25
#define D_  4096
#define H_  512
#define G_  2048   // 4*H
#define M_  6400   // B*T

// Scratch (static __device__ arrays: allocation-free per harness rules)
__device__ float g_zx[(size_t)M_ * G_];        // 52.4 MB
__device__ float g_zr[(size_t)B_ * G_];        // 2 MB   recurrent z per step
__device__ float g_h[B_ * H_];                 // fp32 h (for head)
__device__ float g_c[B_ * H_];
__device__ __half g_a[(size_t)M_ * D_];        // fp16 x
__device__ __half g_b[(size_t)G_ * D_];        // fp16 W^T [N][K]
__device__ __half g_R16[(size_t)G_ * H_];      // fp16 R^T [N=2048][K=512]
__device__ __half g_hhi[B_ * H_];              // fp16 hi(h)
__device__ __half g_hlo[B_ * H_];              // fp16 lo(h)

// grid-barrier state (zero-init; generation-based, safe across graph replays)
__device__ unsigned g_bar_count;
__device__ unsigned g_bar_gen;

typedef unsigned long long u64;

__device__ __forceinline__ uint32_t smem_u32(const void* p) {
    uint32_t a;
    asm("{ .reg .u64 t; cvta.to.shared.u64 t, %1; cvt.u32.u64 %0, t; }" : "=r"(a) : "l"(p));
    return a;
}

// ---------- sm_80-baseline tensor primitives (compute_103-safe) ----------
__device__ __forceinline__ void cp_async16(uint32_t saddr, const void* gaddr) {
    asm volatile("cp.async.cg.shared.global [%0], [%1], 16;" :: "r"(saddr), "l"(gaddr));
}
__device__ __forceinline__ void cp_commit() {
    asm volatile("cp.async.commit_group;" ::: "memory");
}
__device__ __forceinline__ void cp_wait1() {
    asm volatile("cp.async.wait_group 1;" ::: "memory");
}
__device__ __forceinline__ void ldsm4(uint32_t addr, uint32_t* r) {
    asm volatile("ldmatrix.sync.aligned.m8n8.x4.shared.b16 {%0,%1,%2,%3}, [%4];"
        : "=r"(r[0]), "=r"(r[1]), "=r"(r[2]), "=r"(r[3]) : "r"(addr));
}
__device__ __forceinline__ void mma16816(float* c, const uint32_t* a,
                                         uint32_t b0, uint32_t b1) {
    asm volatile("mma.sync.aligned.m16n8k16.row.col.f32.f16.f16.f32 "
        "{%0,%1,%2,%3}, {%4,%5,%6,%7}, {%8,%9}, {%0,%1,%2,%3};"
        : "+f"(c[0]), "+f"(c[1]), "+f"(c[2]), "+f"(c[3])
        : "r"(a[0]), "r"(a[1]), "r"(a[2]), "r"(a[3]), "r"(b0), "r"(b1));
}

__device__ __forceinline__ void split_fp16(float v, __half& h, __half& l) {
    h = __float2half_rn(v);
    l = __float2half_rn(v - __half2float(h));
}

__device__ __forceinline__ uint32_t sw_addr(uint32_t base, int row, int kbyte) {
    int off = row * 128 + kbyte;
    return base + (off ^ ((off >> 3) & 0x70));
}

// Fenced generation grid barrier. All threads fence; thread 0 arrives/spins.
#define NCTAS_SCAN 128
__device__ __forceinline__ void grid_barrier() {
    __threadfence();
    __syncthreads();
    if (threadIdx.x == 0) {
        unsigned gen = atomicAdd(&g_bar_gen, 0u);
        if (atomicAdd(&g_bar_count, 1u) == NCTAS_SCAN - 1u) {
            atomicExch(&g_bar_count, 0u);
            __threadfence();
            atomicAdd(&g_bar_gen, 1u);
        } else {
            while (atomicAdd(&g_bar_gen, 0u) == gen)
                __nanosleep(64);
        }
        __threadfence();
    }
    __syncthreads();
}

// ============================================================================
// prep_R: transpose R [H_, G_] f32 -> g_R16 [G_, H_] fp16
// ============================================================================
__global__ void __launch_bounds__(256) prep_R(const float* __restrict__ R) {
    __shared__ float tile[32][33];
    int tx = threadIdx.x, ty = threadIdx.y;
    int n0 = blockIdx.x * 32, k0 = blockIdx.y * 32;
    #pragma unroll
    for (int j = 0; j < 4; j++)
        tile[ty + j * 8][tx] = R[(size_t)(k0 + ty + j * 8) * G_ + n0 + tx];
    __syncthreads();
    #pragma unroll
    for (int j = 0; j < 4; j++) {
        int n = n0 + ty + j * 8;
        int k = k0 + tx;
        g_R16[(size_t)n * H_ + k] = __float2half_rn(tile[tx][ty + j * 8]);
    }
}

// ============================================================================
// prep_ab: fused prep_a (fp16 x) + prep_b (W transpose->fp16); one launch so
// the scan kernel lands in ncu capture slot #6.
// ============================================================================
#define PREPA_BLOCKS 25600   // M_*D_/4 / 256
#define PREPB_BLOCKS 8192    // (G_/32)*(D_/32)

__global__ void __launch_bounds__(256) prep_ab(const float* __restrict__ x,
                                               const float* __restrict__ W) {
    __shared__ float tile[32][33];
    int bid = blockIdx.x;
    if (bid < PREPA_BLOCKS) {
        size_t idx = (size_t)bid * 256 + threadIdx.x;
        int m  = (int)(idx >> 10);
        int kq = (int)(idx & 1023);
        const float4 v = *(const float4*)(x + ((size_t)(m / T_) * (2 * T_) + (m % T_)) * D_ + kq * 4);
        size_t o = (size_t)m * D_ + kq * 4;
        __half2 p;
        p.x = __float2half_rn(v.x); p.y = __float2half_rn(v.y);
        *(__half2*)(g_a + o) = p;
        p.x = __float2half_rn(v.z); p.y = __float2half_rn(v.w);
        *(__half2*)(g_a + o + 2) = p;
    } else {
        int b2 = bid - PREPA_BLOCKS;
        int tx = threadIdx.x & 31, ty = threadIdx.x >> 5;
        int n0 = (b2 & 63) * 32;     // G_/32 = 64
        int k0 = (b2 >> 6) * 32;     // D_/32 = 128
        #pragma unroll
        for (int j = 0; j < 4; j++)
            tile[ty + j * 8][tx] = W[(size_t)(k0 + ty + j * 8) * G_ + n0 + tx];
        __syncthreads();
        #pragma unroll
        for (int j = 0; j < 4; j++) {
            int n = n0 + ty + j * 8;
            int k = k0 + tx;
            g_b[(size_t)n * D_ + k] = __float2half_rn(tile[tx][ty + j * 8]);
        }
    }
}

// ============================================================================
// gemm_zx_mma: zx = A@B^T + bias  (measured 313us, tensor 56% — left as is)
// ============================================================================
#define NCHUNK   (D_ / 64)    // 64
#define TILE_SZ  16384
#define STAGE_SZ 32768
#define GEMM_SMEM (2 * STAGE_SZ)   // 64KB

__global__ void __launch_bounds__(256, 1) gemm_zx_mma(const float* __restrict__ bias)
{
    extern __shared__ char sm[];
    const uint32_t sbase = smem_u32(sm);
    const int tid = threadIdx.x, wid = tid >> 5, lane = tid & 31;
    const int bn = blockIdx.x, bm = blockIdx.y;

    const __half* gsrc[2];
    gsrc[0] = g_a + (size_t)(bm * 128) * D_;
    gsrc[1] = g_b + (size_t)(bn * 128) * D_;

    int lrow[4], lcol[4];
    uint32_t ssw[4];
    #pragma unroll
    for (int i = 0; i < 4; i++) {
        int q = i * 256 + tid;
        int row = q >> 3, c = q & 7;
        lrow[i] = row; lcol[i] = c * 8;
        int off = row * 128 + c * 16;
        ssw[i] = off ^ ((off >> 3) & 0x70);
    }

    auto issue_stage = [&](int s) {
        const int koff = s * 64;
        const uint32_t stg = sbase + (s & 1) * STAGE_SZ;
        #pragma unroll
        for (int tmat = 0; tmat < 2; tmat++) {
            const __half* gp = gsrc[tmat] + koff;
            uint32_t sp = stg + tmat * TILE_SZ;
            #pragma unroll
            for (int i = 0; i < 4; i++)
                cp_async16(sp + ssw[i], gp + (size_t)lrow[i] * D_ + lcol[i]);
        }
        cp_commit();
    };

    issue_stage(0);
    issue_stage(1);

    const int wm = (wid >> 2) * 64;
    const int wn = (wid & 3) * 32;
    const int lr = lane & 15, khalf = (lane >> 4) * 16;

    float acc[4][4][4];
    #pragma unroll
    for (int a = 0; a < 4; a++)
        #pragma unroll
        for (int b = 0; b < 4; b++)
            #pragma unroll
            for (int r = 0; r < 4; r++) acc[a][b][r] = 0.f;

    for (int c = 0; c < NCHUNK; c++) {
        cp_wait1();
        __syncthreads();
        const uint32_t stg = sbase + (c & 1) * STAGE_SZ;
        const uint32_t sA = stg, sB = stg + TILE_SZ;

        #pragma unroll
        for (int kb = 0; kb < 4; kb++) {
            const int kby = kb * 32 + khalf;
            uint32_t af[4][4], bf[2][4];
            #pragma unroll
            for (int mf = 0; mf < 4; mf++)
                ldsm4(sw_addr(sA, wm + mf * 16 + lr, kby), af[mf]);
            #pragma unroll
            for (int nb = 0; nb < 2; nb++)
                ldsm4(sw_addr(sB, wn + nb * 16 + lr, kby), bf[nb]);
            #pragma unroll
            for (int mf = 0; mf < 4; mf++)
                #pragma unroll
                for (int nf = 0; nf < 4; nf++) {
                    int nb = nf >> 1, sel = nf & 1;
                    mma16816(acc[mf][nf], af[mf], bf[nb][sel], bf[nb][sel + 2]);
                }
        }
        __syncthreads();
        if (c + 2 < NCHUNK) issue_stage(c + 2);
        else cp_commit();
    }

    const int g = lane >> 2, tg = lane & 3;
    #pragma unroll
    for (int mf = 0; mf < 4; mf++) {
        #pragma unroll
        for (int nf = 0; nf < 4; nf++) {
            int m0 = bm * 128 + wm + mf * 16 + g;
            int n0 = bn * 128 + wn + nf * 8 + tg * 2;
            float2 b2 = *(const float2*)&bias[n0];
            float2 v0 = make_float2(acc[mf][nf][0] + b2.x, acc[mf][nf][1] + b2.y);
            float2 v1 = make_float2(acc[mf][nf][2] + b2.x, acc[mf][nf][3] + b2.y);
            *(float2*)(g_zx + (size_t)m0 * G_ + n0)       = v0;
            *(float2*)(g_zx + (size_t)(m0 + 8) * G_ + n0) = v1;
        }
    }
}

// ============================================================================
// lstm_scan: persistent kernel, whole 25-step scan.
// 128 CTAs (co-resident), per step:
//   gemm phase: z_rec tile 64x64 per CTA (grid 4 x 32), h = hhi+hlo fp16,
//               K=512 (8 chunks), warp tile 32x16 (8 warps 2Mx4N)
//   grid barrier; gate phase (4 cells/thread); grid barrier.
// ============================================================================
#define NCHUNK2  (H_ / 64)               // 8
#define SC_TILE  8192                    // 64 rows x 128B
#define SC_STAGE (3 * SC_TILE)           // Ahi, Alo, B = 24KB
#define SCAN_SMEM (2 * SC_STAGE)         // 48KB

__global__ void __launch_bounds__(256, 1) lstm_scan()
{
    extern __shared__ char sm[];
    const uint32_t sbase = smem_u32(sm);
    const int tid = threadIdx.x, wid = tid >> 5, lane = tid & 31;
    const int bid = blockIdx.x;
    const int bm = bid >> 5;     // 0..3   batch tile (64 rows)
    const int bn = bid & 31;     // 0..31  N tile (64 cols)

    // cp.async map: tile = 64 rows x 8 16B-chunks = 512; 2 chunks/thread/tile
    int lrow[2], lcol[2];
    uint32_t ssw[2];
    #pragma unroll
    for (int i = 0; i < 2; i++) {
        int q = i * 256 + tid;
        int row = q >> 3, c = q & 7;
        lrow[i] = row; lcol[i] = c * 8;
        int off = row * 128 + c * 16;
        ssw[i] = off ^ ((off >> 3) & 0x70);
    }

    const __half* srcAh = g_hhi + (size_t)(bm * 64) * H_;
    const __half* srcAl = g_hlo + (size_t)(bm * 64) * H_;
    const __half* srcB  = g_R16 + (size_t)(bn * 64) * H_;

    const int wm = (wid >> 2) * 32;   // 2 M-warps
    const int wn = (wid & 3) * 16;    // 4 N-warps
    const int lr = lane & 15, khalf = (lane >> 4) * 16;
    const int g = lane >> 2, tg = lane & 3;
    const int cell0 = bid * 256 + tid;   // gate-phase base cell

    auto issue_stage = [&](int s) {
        if (s < NCHUNK2) {
            const int koff = s * 64;
            const uint32_t stg = sbase + (s & 1) * SC_STAGE;
            #pragma unroll
            for (int i = 0; i < 2; i++) {
                size_t go = (size_t)lrow[i] * H_ + koff + lcol[i];
                cp_async16(stg +               ssw[i], srcAh + go);
                cp_async16(stg +     SC_TILE + ssw[i], srcAl + go);
                cp_async16(stg + 2 * SC_TILE + ssw[i], srcB  + go);
            }
        }
        cp_commit();
    };

    for (int t = 0; t < T_; t++) {
        if (t > 0) {
            // ---- gemm phase: z_rec(64x64 tile) = [hhi+hlo] @ R^T ----
            float acc[2][2][4];
            #pragma unroll
            for (int a = 0; a < 2; a++)
                #pragma unroll
                for (int b = 0; b < 2; b++)
                    #pragma unroll
                    for (int r = 0; r < 4; r++) acc[a][b][r] = 0.f;

            issue_stage(0);
            issue_stage(1);
            for (int c = 0; c < NCHUNK2; c++) {
                cp_wait1();
                __syncthreads();
                const uint32_t stg = sbase + (c & 1) * SC_STAGE;
                const uint32_t sAh = stg, sAl = stg + SC_TILE, sB = stg + 2 * SC_TILE;

                #pragma unroll
                for (int kb = 0; kb < 4; kb++) {
                    const int kby = kb * 32 + khalf;
                    uint32_t ah[2][4], al[2][4], bf[4];
                    #pragma unroll
                    for (int mf = 0; mf < 2; mf++) {
                        ldsm4(sw_addr(sAh, wm + mf * 16 + lr, kby), ah[mf]);
                        ldsm4(sw_addr(sAl, wm + mf * 16 + lr, kby), al[mf]);
                    }
                    ldsm4(sw_addr(sB, wn + lr, kby), bf);
                    #pragma unroll
                    for (int mf = 0; mf < 2; mf++)
                        #pragma unroll
                        for (int nf = 0; nf < 2; nf++) {
                            mma16816(acc[mf][nf], ah[mf], bf[nf], bf[nf + 2]);
                            mma16816(acc[mf][nf], al[mf], bf[nf], bf[nf + 2]);
                        }
                }
                __syncthreads();
                issue_stage(c + 2);
            }
            // epilogue -> g_zr
            #pragma unroll
            for (int mf = 0; mf < 2; mf++) {
                #pragma unroll
                for (int nf = 0; nf < 2; nf++) {
                    int m0 = bm * 64 + wm + mf * 16 + g;
                    int n0 = bn * 64 + wn + nf * 8 + tg * 2;
                    *(float2*)(g_zr + (size_t)m0 * G_ + n0) =
                        make_float2(acc[mf][nf][0], acc[mf][nf][1]);
                    *(float2*)(g_zr + (size_t)(m0 + 8) * G_ + n0) =
                        make_float2(acc[mf][nf][2], acc[mf][nf][3]);
                }
            }
            grid_barrier();
        }

        // ---- gate phase: 4 cells per thread ----
        #pragma unroll
        for (int p = 0; p < 4; p++) {
            int idx = cell0 + p * 32768;
            int b = idx >> 9;          // batch
            int j = idx & 511;         // hidden unit
            size_t zxrow = (size_t)(b * T_ + t) * G_;
            float zi = g_zx[zxrow + j];
            float zf = g_zx[zxrow + H_ + j];
            float zg = g_zx[zxrow + 2 * H_ + j];
            float zo = g_zx[zxrow + 3 * H_ + j];
            float cp = 0.0f;
            if (t > 0) {
                size_t zrrow = (size_t)b * G_;
                zi += g_zr[zrrow + j];
                zf += g_zr[zrrow + H_ + j];
                zg += g_zr[zrrow + 2 * H_ + j];
                zo += g_zr[zrrow + 3 * H_ + j];
                cp = g_c[b * H_ + j];
            }
            float ig = 1.0f / (1.0f + __expf(-zi));
            float fg = 1.0f / (1.0f + __expf(-zf));
            float gg = 2.0f / (1.0f + __expf(-2.0f * zg)) - 1.0f;
            float og = 1.0f / (1.0f + __expf(-zo));
            float cn = fg * cp + ig * gg;
            float hn = og * (2.0f / (1.0f + __expf(-2.0f * cn)) - 1.0f);
            int ci = b * H_ + j;
            g_c[ci] = cn;
            g_h[ci] = hn;
            __half hh, hl;
            split_fp16(hn, hh, hl);
            g_hhi[ci] = hh;
            g_hlo[ci] = hl;
        }
        if (t + 1 < T_) grid_barrier();   // h complete before next gemm phase
    }
}

// ============================================================================
// head: y = leaky_relu(hT @ w1 + b1); out = softmax(y @ w2 + b2)
// ============================================================================
__global__ void __launch_bounds__(128) head_kernel(
    const float* __restrict__ w1, const float* __restrict__ b1,
    const float* __restrict__ w2, const float* __restrict__ b2,
    float* __restrict__ out)
{
    __shared__ float hs[H_];
    __shared__ float red0[4], red1[4];
    int b = blockIdx.x;
    int tid = threadIdx.x;

    const float* hrow = g_h + (size_t)b * H_;
    *(float4*)&hs[tid * 4] = *(const float4*)&hrow[tid * 4];
    __syncthreads();

    float a0 = 0.f, a1 = 0.f, a2 = 0.f, a3 = 0.f;
    #pragma unroll 4
    for (int k = 0; k < H_; k += 4) {
        a0 += hs[k]     * w1[(size_t)k * 128 + tid];
        a1 += hs[k + 1] * w1[(size_t)(k + 1) * 128 + tid];
        a2 += hs[k + 2] * w1[(size_t)(k + 2) * 128 + tid];
        a3 += hs[k + 3] * w1[(size_t)(k + 3) * 128 + tid];
    }
    float y = a0 + a1 + a2 + a3 + b1[tid];
    y = (y > 0.f) ? y : 0.2f * y;

    float p0 = y * w2[tid * 2];
    float p1 = y * w2[tid * 2 + 1];
    #pragma unroll
    for (int off = 16; off; off >>= 1) {
        p0 += __shfl_xor_sync(0xffffffffu, p0, off);
        p1 += __shfl_xor_sync(0xffffffffu, p1, off);
    }
    int w = tid >> 5;
    if ((tid & 31) == 0) { red0[w] = p0; red1[w] = p1; }
    __syncthreads();
    if (tid == 0) {
        float l0 = red0[0] + red0[1] + red0[2] + red0[3] + b2[0];
        float l1 = red1[0] + red1[1] + red1[2] + red1[3] + b2[1];
        float m = fmaxf(l0, l1);
        float e0 = expf(l0 - m), e1 = expf(l1 - m);
        float s = e0 + e1;
        out[b * 2]     = e0 / s;
        out[b * 2 + 1] = e1 / s;
    }
}

// ============================================================================
extern "C" void kernel_launch(void* const* d_in, const int* in_sizes, int n_in,
                              void* d_out, int out_size)
{
    const float* x    = (const float*)d_in[0];
    const float* W    = (const float*)d_in[1];
    const float* R    = (const float*)d_in[2];
    const float* bias = (const float*)d_in[3];
    const float* w1   = (const float*)d_in[4];
    const float* b1   = (const float*)d_in[5];
    const float* w2   = (const float*)d_in[6];
    const float* b2   = (const float*)d_in[7];
    float* out = (float*)d_out;

    static int configured = 0;
    if (!configured) {
        cudaFuncSetAttribute(gemm_zx_mma,
            cudaFuncAttributeMaxDynamicSharedMemorySize, GEMM_SMEM);
        cudaFuncSetAttribute(lstm_scan,
            cudaFuncAttributeMaxDynamicSharedMemorySize, SCAN_SMEM);
        configured = 1;
    }

    // slots: harness(1,2) prep_R(3) prep_ab(4) gemm_zx(5) lstm_scan(6) -> ncu on scan
    prep_R<<<dim3(G_ / 32, H_ / 32), dim3(32, 8)>>>(R);
    prep_ab<<<PREPA_BLOCKS + PREPB_BLOCKS, 256>>>(x, W);
    gemm_zx_mma<<<dim3(G_ / 128, M_ / 128), 256, GEMM_SMEM>>>(bias);
    lstm_scan<<<NCTAS_SCAN, 256, SCAN_SMEM>>>();
    head_kernel<<<B_, 128>>>(w1, b1, w2, b2, out);
}

// round 15
// speedup vs baseline: 2.0343x; 1.0786x over previous
#include <cuda_runtime.h>
#include <cuda_fp16.h>
#include <cstdint>
#include <math.h>

// Problem dims
#define B_  256
#define T_  25
#define D_  4096
#define H_  512
#define G_  2048   // 4*H
#define M_  6400   // B*T

// Scratch (static __device__ arrays: allocation-free per harness rules)
__device__ float g_zx[(size_t)M_ * G_];        // 52.4 MB
__device__ float g_zr[(size_t)B_ * G_];        // 2 MB   recurrent z per step
__device__ float g_h[B_ * H_];                 // fp32 h (for head)
__device__ float g_c[B_ * H_];
__device__ __half g_a[(size_t)M_ * D_];        // fp16 x
__device__ __half g_b[(size_t)G_ * D_];        // fp16 W^T [N][K]
__device__ __half g_R16[(size_t)G_ * H_];      // fp16 R^T [N=2048][K=512]
__device__ __half g_hhi[B_ * H_];              // fp16 h

// grid-barrier state (zero-init; generation-based)
__device__ unsigned g_bar_count;
__device__ unsigned g_bar_gen;

typedef unsigned long long u64;

__device__ __forceinline__ uint32_t smem_u32(const void* p) {
    uint32_t a;
    asm("{ .reg .u64 t; cvta.to.shared.u64 t, %1; cvt.u32.u64 %0, t; }" : "=r"(a) : "l"(p));
    return a;
}

// ---------- sm_80-baseline tensor primitives (compute_103-safe) ----------
__device__ __forceinline__ void cp_async16(uint32_t saddr, const void* gaddr) {
    asm volatile("cp.async.cg.shared.global [%0], [%1], 16;" :: "r"(saddr), "l"(gaddr));
}
__device__ __forceinline__ void cp_commit() {
    asm volatile("cp.async.commit_group;" ::: "memory");
}
__device__ __forceinline__ void cp_wait1() {
    asm volatile("cp.async.wait_group 1;" ::: "memory");
}
__device__ __forceinline__ void cp_wait0() {
    asm volatile("cp.async.wait_group 0;" ::: "memory");
}
__device__ __forceinline__ void ldsm4(uint32_t addr, uint32_t* r) {
    asm volatile("ldmatrix.sync.aligned.m8n8.x4.shared.b16 {%0,%1,%2,%3}, [%4];"
        : "=r"(r[0]), "=r"(r[1]), "=r"(r[2]), "=r"(r[3]) : "r"(addr));
}
__device__ __forceinline__ void mma16816(float* c, const uint32_t* a,
                                         uint32_t b0, uint32_t b1) {
    asm volatile("mma.sync.aligned.m16n8k16.row.col.f32.f16.f16.f32 "
        "{%0,%1,%2,%3}, {%4,%5,%6,%7}, {%8,%9}, {%0,%1,%2,%3};"
        : "+f"(c[0]), "+f"(c[1]), "+f"(c[2]), "+f"(c[3])
        : "r"(a[0]), "r"(a[1]), "r"(a[2]), "r"(a[3]), "r"(b0), "r"(b1));
}

__device__ __forceinline__ uint32_t sw_addr(uint32_t base, int row, int kbyte) {
    int off = row * 128 + kbyte;
    return base + (off ^ ((off >> 3) & 0x70));
}

// Fenced generation grid barrier.
#define NCTAS_SCAN 128
__device__ __forceinline__ void grid_barrier() {
    __threadfence();
    __syncthreads();
    if (threadIdx.x == 0) {
        unsigned gen = atomicAdd(&g_bar_gen, 0u);
        if (atomicAdd(&g_bar_count, 1u) == NCTAS_SCAN - 1u) {
            atomicExch(&g_bar_count, 0u);
            __threadfence();
            atomicAdd(&g_bar_gen, 1u);
        } else {
            while (atomicAdd(&g_bar_gen, 0u) == gen)
                __nanosleep(64);
        }
        __threadfence();
    }
    __syncthreads();
}

// ============================================================================
// prep_R: transpose R [H_, G_] f32 -> g_R16 [G_, H_] fp16
// ============================================================================
__global__ void __launch_bounds__(256) prep_R(const float* __restrict__ R) {
    __shared__ float tile[32][33];
    int tx = threadIdx.x, ty = threadIdx.y;
    int n0 = blockIdx.x * 32, k0 = blockIdx.y * 32;
    #pragma unroll
    for (int j = 0; j < 4; j++)
        tile[ty + j * 8][tx] = R[(size_t)(k0 + ty + j * 8) * G_ + n0 + tx];
    __syncthreads();
    #pragma unroll
    for (int j = 0; j < 4; j++) {
        int n = n0 + ty + j * 8;
        int k = k0 + tx;
        g_R16[(size_t)n * H_ + k] = __float2half_rn(tile[tx][ty + j * 8]);
    }
}

// ============================================================================
// prep_ab: fused prep_a (fp16 x) + prep_b (W transpose->fp16)
// ============================================================================
#define PREPA_BLOCKS 25600   // M_*D_/4 / 256
#define PREPB_BLOCKS 8192    // (G_/32)*(D_/32)

__global__ void __launch_bounds__(256) prep_ab(const float* __restrict__ x,
                                               const float* __restrict__ W) {
    __shared__ float tile[32][33];
    int bid = blockIdx.x;
    if (bid < PREPA_BLOCKS) {
        size_t idx = (size_t)bid * 256 + threadIdx.x;
        int m  = (int)(idx >> 10);
        int kq = (int)(idx & 1023);
        const float4 v = *(const float4*)(x + ((size_t)(m / T_) * (2 * T_) + (m % T_)) * D_ + kq * 4);
        size_t o = (size_t)m * D_ + kq * 4;
        __half2 p;
        p.x = __float2half_rn(v.x); p.y = __float2half_rn(v.y);
        *(__half2*)(g_a + o) = p;
        p.x = __float2half_rn(v.z); p.y = __float2half_rn(v.w);
        *(__half2*)(g_a + o + 2) = p;
    } else {
        int b2 = bid - PREPA_BLOCKS;
        int tx = threadIdx.x & 31, ty = threadIdx.x >> 5;
        int n0 = (b2 & 63) * 32;
        int k0 = (b2 >> 6) * 32;
        #pragma unroll
        for (int j = 0; j < 4; j++)
            tile[ty + j * 8][tx] = W[(size_t)(k0 + ty + j * 8) * G_ + n0 + tx];
        __syncthreads();
        #pragma unroll
        for (int j = 0; j < 4; j++) {
            int n = n0 + ty + j * 8;
            int k = k0 + tx;
            g_b[(size_t)n * D_ + k] = __float2half_rn(tile[tx][ty + j * 8]);
        }
    }
}

// ============================================================================
// gemm_zx_mma: zx = A@B^T + bias  (measured 313us, tensor 56% — left as is)
// ============================================================================
#define NCHUNK   (D_ / 64)    // 64
#define TILE_SZ  16384
#define STAGE_SZ 32768
#define GEMM_SMEM (2 * STAGE_SZ)   // 64KB

__global__ void __launch_bounds__(256, 1) gemm_zx_mma(const float* __restrict__ bias)
{
    extern __shared__ char sm[];
    const uint32_t sbase = smem_u32(sm);
    const int tid = threadIdx.x, wid = tid >> 5, lane = tid & 31;
    const int bn = blockIdx.x, bm = blockIdx.y;

    const __half* gsrc[2];
    gsrc[0] = g_a + (size_t)(bm * 128) * D_;
    gsrc[1] = g_b + (size_t)(bn * 128) * D_;

    int lrow[4], lcol[4];
    uint32_t ssw[4];
    #pragma unroll
    for (int i = 0; i < 4; i++) {
        int q = i * 256 + tid;
        int row = q >> 3, c = q & 7;
        lrow[i] = row; lcol[i] = c * 8;
        int off = row * 128 + c * 16;
        ssw[i] = off ^ ((off >> 3) & 0x70);
    }

    auto issue_stage = [&](int s) {
        const int koff = s * 64;
        const uint32_t stg = sbase + (s & 1) * STAGE_SZ;
        #pragma unroll
        for (int tmat = 0; tmat < 2; tmat++) {
            const __half* gp = gsrc[tmat] + koff;
            uint32_t sp = stg + tmat * TILE_SZ;
            #pragma unroll
            for (int i = 0; i < 4; i++)
                cp_async16(sp + ssw[i], gp + (size_t)lrow[i] * D_ + lcol[i]);
        }
        cp_commit();
    };

    issue_stage(0);
    issue_stage(1);

    const int wm = (wid >> 2) * 64;
    const int wn = (wid & 3) * 32;
    const int lr = lane & 15, khalf = (lane >> 4) * 16;

    float acc[4][4][4];
    #pragma unroll
    for (int a = 0; a < 4; a++)
        #pragma unroll
        for (int b = 0; b < 4; b++)
            #pragma unroll
            for (int r = 0; r < 4; r++) acc[a][b][r] = 0.f;

    for (int c = 0; c < NCHUNK; c++) {
        cp_wait1();
        __syncthreads();
        const uint32_t stg = sbase + (c & 1) * STAGE_SZ;
        const uint32_t sA = stg, sB = stg + TILE_SZ;

        #pragma unroll
        for (int kb = 0; kb < 4; kb++) {
            const int kby = kb * 32 + khalf;
            uint32_t af[4][4], bf[2][4];
            #pragma unroll
            for (int mf = 0; mf < 4; mf++)
                ldsm4(sw_addr(sA, wm + mf * 16 + lr, kby), af[mf]);
            #pragma unroll
            for (int nb = 0; nb < 2; nb++)
                ldsm4(sw_addr(sB, wn + nb * 16 + lr, kby), bf[nb]);
            #pragma unroll
            for (int mf = 0; mf < 4; mf++)
                #pragma unroll
                for (int nf = 0; nf < 4; nf++) {
                    int nb = nf >> 1, sel = nf & 1;
                    mma16816(acc[mf][nf], af[mf], bf[nb][sel], bf[nb][sel + 2]);
                }
        }
        __syncthreads();
        if (c + 2 < NCHUNK) issue_stage(c + 2);
        else cp_commit();
    }

    const int g = lane >> 2, tg = lane & 3;
    #pragma unroll
    for (int mf = 0; mf < 4; mf++) {
        #pragma unroll
        for (int nf = 0; nf < 4; nf++) {
            int m0 = bm * 128 + wm + mf * 16 + g;
            int n0 = bn * 128 + wn + nf * 8 + tg * 2;
            float2 b2 = *(const float2*)&bias[n0];
            float2 v0 = make_float2(acc[mf][nf][0] + b2.x, acc[mf][nf][1] + b2.y);
            float2 v1 = make_float2(acc[mf][nf][2] + b2.x, acc[mf][nf][3] + b2.y);
            *(float2*)(g_zx + (size_t)m0 * G_ + n0)       = v0;
            *(float2*)(g_zx + (size_t)(m0 + 8) * G_ + n0) = v1;
        }
    }
}

// ============================================================================
// lstm_scan v2: persistent, R smem-RESIDENT, single fp16 h term.
// 128 CTAs (bm 0..3 x bn 0..31), CTA tile 64(M) x 64(N), warp 32x16.
// smem: sR = 64KB (loaded once), sH = 64KB (reloaded per step, one wait).
// Per step: bulk h load -> 32 k16 of pure LDSM/MMA -> epilogue -> barrier ->
// gate phase -> barrier.
// ============================================================================
#define SC_CHUNK 8192                    // 64 rows x 128B per k-chunk
#define SCAN_SMEM (2 * 65536)            // 128KB

__global__ void __launch_bounds__(256, 1) lstm_scan()
{
    extern __shared__ char sm[];
    const uint32_t sbase = smem_u32(sm);
    const uint32_t sR = sbase, sH = sbase + 65536;
    const int tid = threadIdx.x, wid = tid >> 5, lane = tid & 31;
    const int bid = blockIdx.x;
    const int bm = bid >> 5;     // 0..3   batch tile (64 rows)
    const int bn = bid & 31;     // 0..31  N tile (64 cols)

    const __half* srcH = g_hhi + (size_t)(bm * 64) * H_;
    const __half* srcR = g_R16 + (size_t)(bn * 64) * H_;

    // ---- load R tile once (64KB = 4096 16B units, 16/thread) ----
    #pragma unroll
    for (int i = 0; i < 16; i++) {
        int q = i * 256 + tid;
        int c = q >> 9, r = (q >> 3) & 63, u = q & 7;
        int off = r * 128 + u * 16;
        cp_async16(sR + c * SC_CHUNK + (off ^ ((off >> 3) & 0x70)),
                   srcR + (size_t)r * H_ + c * 64 + u * 8);
    }
    cp_commit();

    const int wm = (wid >> 2) * 32;   // 2 M-warps
    const int wn = (wid & 3) * 16;    // 4 N-warps
    const int lr = lane & 15, khalf = (lane >> 4) * 16;
    const int g = lane >> 2, tg = lane & 3;
    const int cell0 = bid * 256 + tid;

    for (int t = 0; t < T_; t++) {
        if (t > 0) {
            // ---- bulk h load (64KB), single wait ----
            #pragma unroll
            for (int i = 0; i < 16; i++) {
                int q = i * 256 + tid;
                int c = q >> 9, r = (q >> 3) & 63, u = q & 7;
                int off = r * 128 + u * 16;
                cp_async16(sH + c * SC_CHUNK + (off ^ ((off >> 3) & 0x70)),
                           srcH + (size_t)r * H_ + c * 64 + u * 8);
            }
            cp_commit();
            cp_wait0();
            __syncthreads();

            // ---- compute: 8 chunks x 4 k16, no waits ----
            float acc[2][2][4];
            #pragma unroll
            for (int a = 0; a < 2; a++)
                #pragma unroll
                for (int b = 0; b < 2; b++)
                    #pragma unroll
                    for (int r = 0; r < 4; r++) acc[a][b][r] = 0.f;

            #pragma unroll
            for (int c = 0; c < 8; c++) {
                const uint32_t cH = sH + c * SC_CHUNK;
                const uint32_t cR = sR + c * SC_CHUNK;
                #pragma unroll
                for (int kb = 0; kb < 4; kb++) {
                    const int kby = kb * 32 + khalf;
                    uint32_t ah[2][4], bf[4];
                    ldsm4(sw_addr(cH, wm + lr, kby), ah[0]);
                    ldsm4(sw_addr(cH, wm + 16 + lr, kby), ah[1]);
                    ldsm4(sw_addr(cR, wn + lr, kby), bf);
                    #pragma unroll
                    for (int mf = 0; mf < 2; mf++)
                        #pragma unroll
                        for (int nf = 0; nf < 2; nf++)
                            mma16816(acc[mf][nf], ah[mf], bf[nf], bf[nf + 2]);
                }
            }
            // epilogue -> g_zr
            #pragma unroll
            for (int mf = 0; mf < 2; mf++) {
                #pragma unroll
                for (int nf = 0; nf < 2; nf++) {
                    int m0 = bm * 64 + wm + mf * 16 + g;
                    int n0 = bn * 64 + wn + nf * 8 + tg * 2;
                    *(float2*)(g_zr + (size_t)m0 * G_ + n0) =
                        make_float2(acc[mf][nf][0], acc[mf][nf][1]);
                    *(float2*)(g_zr + (size_t)(m0 + 8) * G_ + n0) =
                        make_float2(acc[mf][nf][2], acc[mf][nf][3]);
                }
            }
            grid_barrier();
        }

        // ---- gate phase: 4 cells per thread ----
        #pragma unroll
        for (int p = 0; p < 4; p++) {
            int idx = cell0 + p * 32768;
            int b = idx >> 9;
            int j = idx & 511;
            size_t zxrow = (size_t)(b * T_ + t) * G_;
            float zi = g_zx[zxrow + j];
            float zf = g_zx[zxrow + H_ + j];
            float zg = g_zx[zxrow + 2 * H_ + j];
            float zo = g_zx[zxrow + 3 * H_ + j];
            float cp = 0.0f;
            if (t > 0) {
                size_t zrrow = (size_t)b * G_;
                zi += g_zr[zrrow + j];
                zf += g_zr[zrrow + H_ + j];
                zg += g_zr[zrrow + 2 * H_ + j];
                zo += g_zr[zrrow + 3 * H_ + j];
                cp = g_c[b * H_ + j];
            }
            float ig = 1.0f / (1.0f + __expf(-zi));
            float fg = 1.0f / (1.0f + __expf(-zf));
            float gg = 2.0f / (1.0f + __expf(-2.0f * zg)) - 1.0f;
            float og = 1.0f / (1.0f + __expf(-zo));
            float cn = fg * cp + ig * gg;
            float hn = og * (2.0f / (1.0f + __expf(-2.0f * cn)) - 1.0f);
            int ci = b * H_ + j;
            g_c[ci] = cn;
            g_h[ci] = hn;
            g_hhi[ci] = __float2half_rn(hn);
        }
        if (t + 1 < T_) grid_barrier();   // h complete before next gemm phase
    }
}

// ============================================================================
// head: y = leaky_relu(hT @ w1 + b1); out = softmax(y @ w2 + b2)
// ============================================================================
__global__ void __launch_bounds__(128) head_kernel(
    const float* __restrict__ w1, const float* __restrict__ b1,
    const float* __restrict__ w2, const float* __restrict__ b2,
    float* __restrict__ out)
{
    __shared__ float hs[H_];
    __shared__ float red0[4], red1[4];
    int b = blockIdx.x;
    int tid = threadIdx.x;

    const float* hrow = g_h + (size_t)b * H_;
    *(float4*)&hs[tid * 4] = *(const float4*)&hrow[tid * 4];
    __syncthreads();

    float a0 = 0.f, a1 = 0.f, a2 = 0.f, a3 = 0.f;
    #pragma unroll 4
    for (int k = 0; k < H_; k += 4) {
        a0 += hs[k]     * w1[(size_t)k * 128 + tid];
        a1 += hs[k + 1] * w1[(size_t)(k + 1) * 128 + tid];
        a2 += hs[k + 2] * w1[(size_t)(k + 2) * 128 + tid];
        a3 += hs[k + 3] * w1[(size_t)(k + 3) * 128 + tid];
    }
    float y = a0 + a1 + a2 + a3 + b1[tid];
    y = (y > 0.f) ? y : 0.2f * y;

    float p0 = y * w2[tid * 2];
    float p1 = y * w2[tid * 2 + 1];
    #pragma unroll
    for (int off = 16; off; off >>= 1) {
        p0 += __shfl_xor_sync(0xffffffffu, p0, off);
        p1 += __shfl_xor_sync(0xffffffffu, p1, off);
    }
    int w = tid >> 5;
    if ((tid & 31) == 0) { red0[w] = p0; red1[w] = p1; }
    __syncthreads();
    if (tid == 0) {
        float l0 = red0[0] + red0[1] + red0[2] + red0[3] + b2[0];
        float l1 = red1[0] + red1[1] + red1[2] + red1[3] + b2[1];
        float m = fmaxf(l0, l1);
        float e0 = expf(l0 - m), e1 = expf(l1 - m);
        float s = e0 + e1;
        out[b * 2]     = e0 / s;
        out[b * 2 + 1] = e1 / s;
    }
}

// ============================================================================
extern "C" void kernel_launch(void* const* d_in, const int* in_sizes, int n_in,
                              void* d_out, int out_size)
{
    const float* x    = (const float*)d_in[0];
    const float* W    = (const float*)d_in[1];
    const float* R    = (const float*)d_in[2];
    const float* bias = (const float*)d_in[3];
    const float* w1   = (const float*)d_in[4];
    const float* b1   = (const float*)d_in[5];
    const float* w2   = (const float*)d_in[6];
    const float* b2   = (const float*)d_in[7];
    float* out = (float*)d_out;

    static int configured = 0;
    if (!configured) {
        cudaFuncSetAttribute(gemm_zx_mma,
            cudaFuncAttributeMaxDynamicSharedMemorySize, GEMM_SMEM);
        cudaFuncSetAttribute(lstm_scan,
            cudaFuncAttributeMaxDynamicSharedMemorySize, SCAN_SMEM);
        configured = 1;
    }

    // slots: harness(1,2) prep_R(3) prep_ab(4) gemm_zx(5) lstm_scan(6) -> ncu on scan
    prep_R<<<dim3(G_ / 32, H_ / 32), dim3(32, 8)>>>(R);
    prep_ab<<<PREPA_BLOCKS + PREPB_BLOCKS, 256>>>(x, W);
    gemm_zx_mma<<<dim3(G_ / 128, M_ / 128), 256, GEMM_SMEM>>>(bias);
    lstm_scan<<<NCTAS_SCAN, 256, SCAN_SMEM>>>();
    head_kernel<<<B_, 128>>>(w1, b1, w2, b2, out);
}

// round 16
// speedup vs baseline: 2.2223x; 1.0924x over previous
#include <cuda_runtime.h>
#include <cuda_fp16.h>
#include <cstdint>
#include <math.h>

// Problem dims
#define B_  256
#define T_  25
#define D_  4096
#define H_  512
#define G_  2048   // 4*H
#define M_  6400   // B*T

// Scratch (static __device__ arrays: allocation-free per harness rules)
__device__ float g_zx[(size_t)M_ * G_];        // 52.4 MB
__device__ float g_h[B_ * H_];                 // fp32 h (for head)
__device__ float g_c[B_ * H_];
__device__ __half g_a[(size_t)M_ * D_];        // fp16 x
__device__ __half g_b[(size_t)G_ * D_];        // fp16 W^T [N][K]
__device__ __half g_R16[(size_t)G_ * H_];      // fp16 R^T, GATE-INTERLEAVED rows
__device__ __half g_hhi[B_ * H_];              // fp16 h

// grid-barrier state (zero-init; generation-based)
__device__ unsigned g_bar_count;
__device__ unsigned g_bar_gen;

typedef unsigned long long u64;

__device__ __forceinline__ uint32_t smem_u32(const void* p) {
    uint32_t a;
    asm("{ .reg .u64 t; cvta.to.shared.u64 t, %1; cvt.u32.u64 %0, t; }" : "=r"(a) : "l"(p));
    return a;
}

// ---------- sm_80-baseline tensor primitives (compute_103-safe) ----------
__device__ __forceinline__ void cp_async16(uint32_t saddr, const void* gaddr) {
    asm volatile("cp.async.cg.shared.global [%0], [%1], 16;" :: "r"(saddr), "l"(gaddr));
}
__device__ __forceinline__ void cp_commit() {
    asm volatile("cp.async.commit_group;" ::: "memory");
}
__device__ __forceinline__ void cp_wait1() {
    asm volatile("cp.async.wait_group 1;" ::: "memory");
}
__device__ __forceinline__ void cp_wait0() {
    asm volatile("cp.async.wait_group 0;" ::: "memory");
}
__device__ __forceinline__ void ldsm4(uint32_t addr, uint32_t* r) {
    asm volatile("ldmatrix.sync.aligned.m8n8.x4.shared.b16 {%0,%1,%2,%3}, [%4];"
        : "=r"(r[0]), "=r"(r[1]), "=r"(r[2]), "=r"(r[3]) : "r"(addr));
}
__device__ __forceinline__ void mma16816(float* c, const uint32_t* a,
                                         uint32_t b0, uint32_t b1) {
    asm volatile("mma.sync.aligned.m16n8k16.row.col.f32.f16.f16.f32 "
        "{%0,%1,%2,%3}, {%4,%5,%6,%7}, {%8,%9}, {%0,%1,%2,%3};"
        : "+f"(c[0]), "+f"(c[1]), "+f"(c[2]), "+f"(c[3])
        : "r"(a[0]), "r"(a[1]), "r"(a[2]), "r"(a[3]), "r"(b0), "r"(b1));
}

__device__ __forceinline__ uint32_t sw_addr(uint32_t base, int row, int kbyte) {
    int off = row * 128 + kbyte;
    return base + (off ^ ((off >> 3) & 0x70));
}

// Fenced generation grid barrier.
#define NCTAS_SCAN 128
__device__ __forceinline__ void grid_barrier() {
    __threadfence();
    __syncthreads();
    if (threadIdx.x == 0) {
        unsigned gen = atomicAdd(&g_bar_gen, 0u);
        if (atomicAdd(&g_bar_count, 1u) == NCTAS_SCAN - 1u) {
            atomicExch(&g_bar_count, 0u);
            __threadfence();
            atomicAdd(&g_bar_gen, 1u);
        } else {
            while (atomicAdd(&g_bar_gen, 0u) == gen)
                __nanosleep(64);
        }
        __threadfence();
    }
    __syncthreads();
}

// ============================================================================
// prep_R: transpose R [H_, G_] f32 -> g_R16 fp16 with GATE-INTERLEAVED rows:
//   original col n = g*512 + u  ->  row pn = (u/16)*64 + g*16 + (u%16)
// so scan-CTA bn owns rows [bn*64, bn*64+64) = 16 units x 4 gates (local g*16+jj).
// ============================================================================
__global__ void __launch_bounds__(256) prep_R(const float* __restrict__ R) {
    __shared__ float tile[32][33];
    int tx = threadIdx.x, ty = threadIdx.y;
    int n0 = blockIdx.x * 32, k0 = blockIdx.y * 32;
    #pragma unroll
    for (int j = 0; j < 4; j++)
        tile[ty + j * 8][tx] = R[(size_t)(k0 + ty + j * 8) * G_ + n0 + tx];
    __syncthreads();
    #pragma unroll
    for (int j = 0; j < 4; j++) {
        int n = n0 + ty + j * 8;
        int k = k0 + tx;
        int g = n >> 9, u = n & 511;
        int pn = (u >> 4) * 64 + g * 16 + (u & 15);
        g_R16[(size_t)pn * H_ + k] = __float2half_rn(tile[tx][ty + j * 8]);
    }
}

// ============================================================================
// prep_ab: fused prep_a (fp16 x) + prep_b (W transpose->fp16)
// ============================================================================
#define PREPA_BLOCKS 25600   // M_*D_/4 / 256
#define PREPB_BLOCKS 8192    // (G_/32)*(D_/32)

__global__ void __launch_bounds__(256) prep_ab(const float* __restrict__ x,
                                               const float* __restrict__ W) {
    __shared__ float tile[32][33];
    int bid = blockIdx.x;
    if (bid < PREPA_BLOCKS) {
        size_t idx = (size_t)bid * 256 + threadIdx.x;
        int m  = (int)(idx >> 10);
        int kq = (int)(idx & 1023);
        const float4 v = *(const float4*)(x + ((size_t)(m / T_) * (2 * T_) + (m % T_)) * D_ + kq * 4);
        size_t o = (size_t)m * D_ + kq * 4;
        __half2 p;
        p.x = __float2half_rn(v.x); p.y = __float2half_rn(v.y);
        *(__half2*)(g_a + o) = p;
        p.x = __float2half_rn(v.z); p.y = __float2half_rn(v.w);
        *(__half2*)(g_a + o + 2) = p;
    } else {
        int b2 = bid - PREPA_BLOCKS;
        int tx = threadIdx.x & 31, ty = threadIdx.x >> 5;
        int n0 = (b2 & 63) * 32;
        int k0 = (b2 >> 6) * 32;
        #pragma unroll
        for (int j = 0; j < 4; j++)
            tile[ty + j * 8][tx] = W[(size_t)(k0 + ty + j * 8) * G_ + n0 + tx];
        __syncthreads();
        #pragma unroll
        for (int j = 0; j < 4; j++) {
            int n = n0 + ty + j * 8;
            int k = k0 + tx;
            g_b[(size_t)n * D_ + k] = __float2half_rn(tile[tx][ty + j * 8]);
        }
    }
}

// ============================================================================
// gemm_zx_mma: zx = A@B^T + bias  (measured 313us, tensor 56% — left as is)
// ============================================================================
#define NCHUNK   (D_ / 64)    // 64
#define TILE_SZ  16384
#define STAGE_SZ 32768
#define GEMM_SMEM (2 * STAGE_SZ)   // 64KB

__global__ void __launch_bounds__(256, 1) gemm_zx_mma(const float* __restrict__ bias)
{
    extern __shared__ char sm[];
    const uint32_t sbase = smem_u32(sm);
    const int tid = threadIdx.x, wid = tid >> 5, lane = tid & 31;
    const int bn = blockIdx.x, bm = blockIdx.y;

    const __half* gsrc[2];
    gsrc[0] = g_a + (size_t)(bm * 128) * D_;
    gsrc[1] = g_b + (size_t)(bn * 128) * D_;

    int lrow[4], lcol[4];
    uint32_t ssw[4];
    #pragma unroll
    for (int i = 0; i < 4; i++) {
        int q = i * 256 + tid;
        int row = q >> 3, c = q & 7;
        lrow[i] = row; lcol[i] = c * 8;
        int off = row * 128 + c * 16;
        ssw[i] = off ^ ((off >> 3) & 0x70);
    }

    auto issue_stage = [&](int s) {
        const int koff = s * 64;
        const uint32_t stg = sbase + (s & 1) * STAGE_SZ;
        #pragma unroll
        for (int tmat = 0; tmat < 2; tmat++) {
            const __half* gp = gsrc[tmat] + koff;
            uint32_t sp = stg + tmat * TILE_SZ;
            #pragma unroll
            for (int i = 0; i < 4; i++)
                cp_async16(sp + ssw[i], gp + (size_t)lrow[i] * D_ + lcol[i]);
        }
        cp_commit();
    };

    issue_stage(0);
    issue_stage(1);

    const int wm = (wid >> 2) * 64;
    const int wn = (wid & 3) * 32;
    const int lr = lane & 15, khalf = (lane >> 4) * 16;

    float acc[4][4][4];
    #pragma unroll
    for (int a = 0; a < 4; a++)
        #pragma unroll
        for (int b = 0; b < 4; b++)
            #pragma unroll
            for (int r = 0; r < 4; r++) acc[a][b][r] = 0.f;

    for (int c = 0; c < NCHUNK; c++) {
        cp_wait1();
        __syncthreads();
        const uint32_t stg = sbase + (c & 1) * STAGE_SZ;
        const uint32_t sA = stg, sB = stg + TILE_SZ;

        #pragma unroll
        for (int kb = 0; kb < 4; kb++) {
            const int kby = kb * 32 + khalf;
            uint32_t af[4][4], bf[2][4];
            #pragma unroll
            for (int mf = 0; mf < 4; mf++)
                ldsm4(sw_addr(sA, wm + mf * 16 + lr, kby), af[mf]);
            #pragma unroll
            for (int nb = 0; nb < 2; nb++)
                ldsm4(sw_addr(sB, wn + nb * 16 + lr, kby), bf[nb]);
            #pragma unroll
            for (int mf = 0; mf < 4; mf++)
                #pragma unroll
                for (int nf = 0; nf < 4; nf++) {
                    int nb = nf >> 1, sel = nf & 1;
                    mma16816(acc[mf][nf], af[mf], bf[nb][sel], bf[nb][sel + 2]);
                }
        }
        __syncthreads();
        if (c + 2 < NCHUNK) issue_stage(c + 2);
        else cp_commit();
    }

    const int g = lane >> 2, tg = lane & 3;
    #pragma unroll
    for (int mf = 0; mf < 4; mf++) {
        #pragma unroll
        for (int nf = 0; nf < 4; nf++) {
            int m0 = bm * 128 + wm + mf * 16 + g;
            int n0 = bn * 128 + wn + nf * 8 + tg * 2;
            float2 b2 = *(const float2*)&bias[n0];
            float2 v0 = make_float2(acc[mf][nf][0] + b2.x, acc[mf][nf][1] + b2.y);
            float2 v1 = make_float2(acc[mf][nf][2] + b2.x, acc[mf][nf][3] + b2.y);
            *(float2*)(g_zx + (size_t)m0 * G_ + n0)       = v0;
            *(float2*)(g_zx + (size_t)(m0 + 8) * G_ + n0) = v1;
        }
    }
}

// ============================================================================
// lstm_scan v3: persistent, R smem-resident (gate-interleaved), FUSED gate
// phase (no z_rec global round trip), ONE grid barrier per step.
// 128 CTAs: bm 0..3 (64 batches) x bn 0..31 (16 units x 4 gates = 64 N-cols).
// ============================================================================
#define SC_CHUNK 8192                    // 64 rows x 128B per k-chunk
#define SCAN_SMEM (2 * 65536 + 16384)    // sR 64K + sH 64K + zsm 16K

__global__ void __launch_bounds__(256, 1) lstm_scan()
{
    extern __shared__ char sm[];
    const uint32_t sbase = smem_u32(sm);
    const uint32_t sR = sbase, sH = sbase + 65536;
    float (*zsm)[64] = (float(*)[64])(sm + 2 * 65536);
    const int tid = threadIdx.x, wid = tid >> 5, lane = tid & 31;
    const int bid = blockIdx.x;
    const int bm = bid >> 5;     // 0..3   batch tile (64 rows)
    const int bn = bid & 31;     // 0..31  unit tile (16 units x 4 gates)

    const __half* srcH = g_hhi + (size_t)(bm * 64) * H_;
    const __half* srcR = g_R16 + (size_t)(bn * 64) * H_;

    // ---- load R tile once (64KB) ----
    #pragma unroll
    for (int i = 0; i < 16; i++) {
        int q = i * 256 + tid;
        int c = q >> 9, r = (q >> 3) & 63, u = q & 7;
        int off = r * 128 + u * 16;
        cp_async16(sR + c * SC_CHUNK + (off ^ ((off >> 3) & 0x70)),
                   srcR + (size_t)r * H_ + c * 64 + u * 8);
    }
    cp_commit();

    const int wm = (wid >> 2) * 32;   // 2 M-warps
    const int wn = (wid & 3) * 16;    // 4 N-warps
    const int lr = lane & 15, khalf = (lane >> 4) * 16;
    const int g = lane >> 2, tg = lane & 3;

    for (int t = 0; t < T_; t++) {
        if (t > 0) {
            // ---- bulk h load (64KB), single wait ----
            #pragma unroll
            for (int i = 0; i < 16; i++) {
                int q = i * 256 + tid;
                int c = q >> 9, r = (q >> 3) & 63, u = q & 7;
                int off = r * 128 + u * 16;
                cp_async16(sH + c * SC_CHUNK + (off ^ ((off >> 3) & 0x70)),
                           srcH + (size_t)r * H_ + c * 64 + u * 8);
            }
            cp_commit();
            cp_wait0();
            __syncthreads();

            // ---- gemm: zsm(64x64) = h(64x512) @ Rperm^T ----
            float acc[2][2][4];
            #pragma unroll
            for (int a = 0; a < 2; a++)
                #pragma unroll
                for (int b = 0; b < 2; b++)
                    #pragma unroll
                    for (int r = 0; r < 4; r++) acc[a][b][r] = 0.f;

            #pragma unroll
            for (int c = 0; c < 8; c++) {
                const uint32_t cH = sH + c * SC_CHUNK;
                const uint32_t cR = sR + c * SC_CHUNK;
                #pragma unroll
                for (int kb = 0; kb < 4; kb++) {
                    const int kby = kb * 32 + khalf;
                    uint32_t ah[2][4], bf[4];
                    ldsm4(sw_addr(cH, wm + lr, kby), ah[0]);
                    ldsm4(sw_addr(cH, wm + 16 + lr, kby), ah[1]);
                    ldsm4(sw_addr(cR, wn + lr, kby), bf);
                    #pragma unroll
                    for (int mf = 0; mf < 2; mf++)
                        #pragma unroll
                        for (int nf = 0; nf < 2; nf++)
                            mma16816(acc[mf][nf], ah[mf], bf[nf], bf[nf + 2]);
                }
            }
            // epilogue -> zsm (in-CTA)
            #pragma unroll
            for (int mf = 0; mf < 2; mf++) {
                #pragma unroll
                for (int nf = 0; nf < 2; nf++) {
                    int ml = wm + mf * 16 + g;
                    int nl = wn + nf * 8 + tg * 2;
                    zsm[ml][nl]     = acc[mf][nf][0];
                    zsm[ml][nl + 1] = acc[mf][nf][1];
                    zsm[ml + 8][nl]     = acc[mf][nf][2];
                    zsm[ml + 8][nl + 1] = acc[mf][nf][3];
                }
            }
            __syncthreads();
        }

        // ---- fused gate phase: 1024 cells/CTA (64 batches x 16 units), 4/thread
        #pragma unroll
        for (int p = 0; p < 4; p++) {
            int lin = p * 256 + tid;
            int lb = lin >> 4;          // 0..63 local batch
            int jj = lin & 15;          // 0..15 local unit
            int b = bm * 64 + lb;
            int col = bn * 16 + jj;     // global unit
            size_t zxrow = (size_t)(b * T_ + t) * G_;
            float zi = g_zx[zxrow + col];
            float zf = g_zx[zxrow + H_ + col];
            float zg = g_zx[zxrow + 2 * H_ + col];
            float zo = g_zx[zxrow + 3 * H_ + col];
            float cp = 0.0f;
            if (t > 0) {
                zi += zsm[lb][jj];
                zf += zsm[lb][16 + jj];
                zg += zsm[lb][32 + jj];
                zo += zsm[lb][48 + jj];
                cp = g_c[b * H_ + col];
            }
            float ig = 1.0f / (1.0f + __expf(-zi));
            float fg = 1.0f / (1.0f + __expf(-zf));
            float gg = 2.0f / (1.0f + __expf(-2.0f * zg)) - 1.0f;
            float og = 1.0f / (1.0f + __expf(-zo));
            float cn = fg * cp + ig * gg;
            float hn = og * (2.0f / (1.0f + __expf(-2.0f * cn)) - 1.0f);
            int ci = b * H_ + col;
            g_c[ci] = cn;
            g_h[ci] = hn;
            g_hhi[ci] = __float2half_rn(hn);
        }
        if (t + 1 < T_) grid_barrier();   // h visible before next step's h load
    }
}

// ============================================================================
// head: y = leaky_relu(hT @ w1 + b1); out = softmax(y @ w2 + b2)
// ============================================================================
__global__ void __launch_bounds__(128) head_kernel(
    const float* __restrict__ w1, const float* __restrict__ b1,
    const float* __restrict__ w2, const float* __restrict__ b2,
    float* __restrict__ out)
{
    __shared__ float hs[H_];
    __shared__ float red0[4], red1[4];
    int b = blockIdx.x;
    int tid = threadIdx.x;

    const float* hrow = g_h + (size_t)b * H_;
    *(float4*)&hs[tid * 4] = *(const float4*)&hrow[tid * 4];
    __syncthreads();

    float a0 = 0.f, a1 = 0.f, a2 = 0.f, a3 = 0.f;
    #pragma unroll 4
    for (int k = 0; k < H_; k += 4) {
        a0 += hs[k]     * w1[(size_t)k * 128 + tid];
        a1 += hs[k + 1] * w1[(size_t)(k + 1) * 128 + tid];
        a2 += hs[k + 2] * w1[(size_t)(k + 2) * 128 + tid];
        a3 += hs[k + 3] * w1[(size_t)(k + 3) * 128 + tid];
    }
    float y = a0 + a1 + a2 + a3 + b1[tid];
    y = (y > 0.f) ? y : 0.2f * y;

    float p0 = y * w2[tid * 2];
    float p1 = y * w2[tid * 2 + 1];
    #pragma unroll
    for (int off = 16; off; off >>= 1) {
        p0 += __shfl_xor_sync(0xffffffffu, p0, off);
        p1 += __shfl_xor_sync(0xffffffffu, p1, off);
    }
    int w = tid >> 5;
    if ((tid & 31) == 0) { red0[w] = p0; red1[w] = p1; }
    __syncthreads();
    if (tid == 0) {
        float l0 = red0[0] + red0[1] + red0[2] + red0[3] + b2[0];
        float l1 = red1[0] + red1[1] + red1[2] + red1[3] + b2[1];
        float m = fmaxf(l0, l1);
        float e0 = expf(l0 - m), e1 = expf(l1 - m);
        float s = e0 + e1;
        out[b * 2]     = e0 / s;
        out[b * 2 + 1] = e1 / s;
    }
}

// ============================================================================
extern "C" void kernel_launch(void* const* d_in, const int* in_sizes, int n_in,
                              void* d_out, int out_size)
{
    const float* x    = (const float*)d_in[0];
    const float* W    = (const float*)d_in[1];
    const float* R    = (const float*)d_in[2];
    const float* bias = (const float*)d_in[3];
    const float* w1   = (const float*)d_in[4];
    const float* b1   = (const float*)d_in[5];
    const float* w2   = (const float*)d_in[6];
    const float* b2   = (const float*)d_in[7];
    float* out = (float*)d_out;

    static int configured = 0;
    if (!configured) {
        cudaFuncSetAttribute(gemm_zx_mma,
            cudaFuncAttributeMaxDynamicSharedMemorySize, GEMM_SMEM);
        cudaFuncSetAttribute(lstm_scan,
            cudaFuncAttributeMaxDynamicSharedMemorySize, SCAN_SMEM);
        configured = 1;
    }

    // slots: harness(1,2) prep_R(3) prep_ab(4) gemm_zx(5) lstm_scan(6) -> ncu on scan
    prep_R<<<dim3(G_ / 32, H_ / 32), dim3(32, 8)>>>(R);
    prep_ab<<<PREPA_BLOCKS + PREPB_BLOCKS, 256>>>(x, W);
    gemm_zx_mma<<<dim3(G_ / 128, M_ / 128), 256, GEMM_SMEM>>>(bias);
    lstm_scan<<<NCTAS_SCAN, 256, SCAN_SMEM>>>();
    head_kernel<<<B_, 128>>>(w1, b1, w2, b2, out);
}

// round 17
// speedup vs baseline: 2.3268x; 1.0470x over previous
#include <cuda_runtime.h>
#include <cuda_fp16.h>
#include <cstdint>
#include <math.h>

// Problem dims
#define B_  256
#define T_  25
#define D_  4096
#define H_  512
#define G_  2048   // 4*H
#define M_  6400   // B*T

// Scratch (static __device__ arrays: allocation-free per harness rules)
__device__ float g_zx[(size_t)M_ * G_];        // 52.4 MB
__device__ float g_h[B_ * H_];                 // fp32 h (for head)
__device__ float g_c[B_ * H_];
__device__ __half g_a[(size_t)M_ * D_];        // fp16 x
__device__ __half g_b[(size_t)G_ * D_];        // fp16 W^T [N][K]
__device__ __half g_R16[(size_t)G_ * H_];      // fp16 R^T, GATE-INTERLEAVED rows
__device__ __half g_hhi[B_ * H_];              // fp16 h

// grid-barrier state (zero-init; generation-based)
__device__ unsigned g_bar_count;
__device__ unsigned g_bar_gen;

typedef unsigned long long u64;

__device__ __forceinline__ uint32_t smem_u32(const void* p) {
    uint32_t a;
    asm("{ .reg .u64 t; cvta.to.shared.u64 t, %1; cvt.u32.u64 %0, t; }" : "=r"(a) : "l"(p));
    return a;
}

// ---------- sm_80-baseline tensor primitives (compute_103-safe) ----------
__device__ __forceinline__ void cp_async16(uint32_t saddr, const void* gaddr) {
    asm volatile("cp.async.cg.shared.global [%0], [%1], 16;" :: "r"(saddr), "l"(gaddr));
}
__device__ __forceinline__ void cp_commit() {
    asm volatile("cp.async.commit_group;" ::: "memory");
}
__device__ __forceinline__ void cp_wait1() {
    asm volatile("cp.async.wait_group 1;" ::: "memory");
}
__device__ __forceinline__ void cp_wait0() {
    asm volatile("cp.async.wait_group 0;" ::: "memory");
}
__device__ __forceinline__ void ldsm4(uint32_t addr, uint32_t* r) {
    asm volatile("ldmatrix.sync.aligned.m8n8.x4.shared.b16 {%0,%1,%2,%3}, [%4];"
        : "=r"(r[0]), "=r"(r[1]), "=r"(r[2]), "=r"(r[3]) : "r"(addr));
}
__device__ __forceinline__ void mma16816(float* c, const uint32_t* a,
                                         uint32_t b0, uint32_t b1) {
    asm volatile("mma.sync.aligned.m16n8k16.row.col.f32.f16.f16.f32 "
        "{%0,%1,%2,%3}, {%4,%5,%6,%7}, {%8,%9}, {%0,%1,%2,%3};"
        : "+f"(c[0]), "+f"(c[1]), "+f"(c[2]), "+f"(c[3])
        : "r"(a[0]), "r"(a[1]), "r"(a[2]), "r"(a[3]), "r"(b0), "r"(b1));
}

// 1-MUFU tanh (sm_75+ MUFU.TANH; max abs err ~2^-11)
__device__ __forceinline__ float tanh_fast(float x) {
    float y; asm("tanh.approx.f32 %0, %1;" : "=f"(y) : "f"(x)); return y;
}
// sigmoid via tanh: 1 MUFU instead of EX2+RCP
__device__ __forceinline__ float sigmoid_fast(float x) {
    return 0.5f + 0.5f * tanh_fast(0.5f * x);
}

__device__ __forceinline__ uint32_t sw_addr(uint32_t base, int row, int kbyte) {
    int off = row * 128 + kbyte;
    return base + (off ^ ((off >> 3) & 0x70));
}

// Fenced generation grid barrier.
#define NCTAS_SCAN 128
__device__ __forceinline__ void grid_barrier() {
    __threadfence();
    __syncthreads();
    if (threadIdx.x == 0) {
        unsigned gen = atomicAdd(&g_bar_gen, 0u);
        if (atomicAdd(&g_bar_count, 1u) == NCTAS_SCAN - 1u) {
            atomicExch(&g_bar_count, 0u);
            __threadfence();
            atomicAdd(&g_bar_gen, 1u);
        } else {
            while (atomicAdd(&g_bar_gen, 0u) == gen)
                __nanosleep(64);
        }
        __threadfence();
    }
    __syncthreads();
}

// ============================================================================
// prep_R: transpose R [H_, G_] f32 -> g_R16 fp16 with GATE-INTERLEAVED rows:
//   original col n = g*512 + u  ->  row pn = (u/16)*64 + g*16 + (u%16)
// ============================================================================
__global__ void __launch_bounds__(256) prep_R(const float* __restrict__ R) {
    __shared__ float tile[32][33];
    int tx = threadIdx.x, ty = threadIdx.y;
    int n0 = blockIdx.x * 32, k0 = blockIdx.y * 32;
    #pragma unroll
    for (int j = 0; j < 4; j++)
        tile[ty + j * 8][tx] = R[(size_t)(k0 + ty + j * 8) * G_ + n0 + tx];
    __syncthreads();
    #pragma unroll
    for (int j = 0; j < 4; j++) {
        int n = n0 + ty + j * 8;
        int k = k0 + tx;
        int g = n >> 9, u = n & 511;
        int pn = (u >> 4) * 64 + g * 16 + (u & 15);
        g_R16[(size_t)pn * H_ + k] = __float2half_rn(tile[tx][ty + j * 8]);
    }
}

// ============================================================================
// prep_ab: fused prep_a (fp16 x) + prep_b (W transpose->fp16)
// ============================================================================
#define PREPA_BLOCKS 25600   // M_*D_/4 / 256
#define PREPB_BLOCKS 8192    // (G_/32)*(D_/32)

__global__ void __launch_bounds__(256) prep_ab(const float* __restrict__ x,
                                               const float* __restrict__ W) {
    __shared__ float tile[32][33];
    int bid = blockIdx.x;
    if (bid < PREPA_BLOCKS) {
        size_t idx = (size_t)bid * 256 + threadIdx.x;
        int m  = (int)(idx >> 10);
        int kq = (int)(idx & 1023);
        const float4 v = *(const float4*)(x + ((size_t)(m / T_) * (2 * T_) + (m % T_)) * D_ + kq * 4);
        size_t o = (size_t)m * D_ + kq * 4;
        __half2 p;
        p.x = __float2half_rn(v.x); p.y = __float2half_rn(v.y);
        *(__half2*)(g_a + o) = p;
        p.x = __float2half_rn(v.z); p.y = __float2half_rn(v.w);
        *(__half2*)(g_a + o + 2) = p;
    } else {
        int b2 = bid - PREPA_BLOCKS;
        int tx = threadIdx.x & 31, ty = threadIdx.x >> 5;
        int n0 = (b2 & 63) * 32;
        int k0 = (b2 >> 6) * 32;
        #pragma unroll
        for (int j = 0; j < 4; j++)
            tile[ty + j * 8][tx] = W[(size_t)(k0 + ty + j * 8) * G_ + n0 + tx];
        __syncthreads();
        #pragma unroll
        for (int j = 0; j < 4; j++) {
            int n = n0 + ty + j * 8;
            int k = k0 + tx;
            g_b[(size_t)n * D_ + k] = __float2half_rn(tile[tx][ty + j * 8]);
        }
    }
}

// ============================================================================
// gemm_zx_mma: zx = A@B^T + bias  (measured 313us, tensor 56% — left as is)
// ============================================================================
#define NCHUNK   (D_ / 64)    // 64
#define TILE_SZ  16384
#define STAGE_SZ 32768
#define GEMM_SMEM (2 * STAGE_SZ)   // 64KB

__global__ void __launch_bounds__(256, 1) gemm_zx_mma(const float* __restrict__ bias)
{
    extern __shared__ char sm[];
    const uint32_t sbase = smem_u32(sm);
    const int tid = threadIdx.x, wid = tid >> 5, lane = tid & 31;
    const int bn = blockIdx.x, bm = blockIdx.y;

    const __half* gsrc[2];
    gsrc[0] = g_a + (size_t)(bm * 128) * D_;
    gsrc[1] = g_b + (size_t)(bn * 128) * D_;

    int lrow[4], lcol[4];
    uint32_t ssw[4];
    #pragma unroll
    for (int i = 0; i < 4; i++) {
        int q = i * 256 + tid;
        int row = q >> 3, c = q & 7;
        lrow[i] = row; lcol[i] = c * 8;
        int off = row * 128 + c * 16;
        ssw[i] = off ^ ((off >> 3) & 0x70);
    }

    auto issue_stage = [&](int s) {
        const int koff = s * 64;
        const uint32_t stg = sbase + (s & 1) * STAGE_SZ;
        #pragma unroll
        for (int tmat = 0; tmat < 2; tmat++) {
            const __half* gp = gsrc[tmat] + koff;
            uint32_t sp = stg + tmat * TILE_SZ;
            #pragma unroll
            for (int i = 0; i < 4; i++)
                cp_async16(sp + ssw[i], gp + (size_t)lrow[i] * D_ + lcol[i]);
        }
        cp_commit();
    };

    issue_stage(0);
    issue_stage(1);

    const int wm = (wid >> 2) * 64;
    const int wn = (wid & 3) * 32;
    const int lr = lane & 15, khalf = (lane >> 4) * 16;

    float acc[4][4][4];
    #pragma unroll
    for (int a = 0; a < 4; a++)
        #pragma unroll
        for (int b = 0; b < 4; b++)
            #pragma unroll
            for (int r = 0; r < 4; r++) acc[a][b][r] = 0.f;

    for (int c = 0; c < NCHUNK; c++) {
        cp_wait1();
        __syncthreads();
        const uint32_t stg = sbase + (c & 1) * STAGE_SZ;
        const uint32_t sA = stg, sB = stg + TILE_SZ;

        #pragma unroll
        for (int kb = 0; kb < 4; kb++) {
            const int kby = kb * 32 + khalf;
            uint32_t af[4][4], bf[2][4];
            #pragma unroll
            for (int mf = 0; mf < 4; mf++)
                ldsm4(sw_addr(sA, wm + mf * 16 + lr, kby), af[mf]);
            #pragma unroll
            for (int nb = 0; nb < 2; nb++)
                ldsm4(sw_addr(sB, wn + nb * 16 + lr, kby), bf[nb]);
            #pragma unroll
            for (int mf = 0; mf < 4; mf++)
                #pragma unroll
                for (int nf = 0; nf < 4; nf++) {
                    int nb = nf >> 1, sel = nf & 1;
                    mma16816(acc[mf][nf], af[mf], bf[nb][sel], bf[nb][sel + 2]);
                }
        }
        __syncthreads();
        if (c + 2 < NCHUNK) issue_stage(c + 2);
        else cp_commit();
    }

    const int g = lane >> 2, tg = lane & 3;
    #pragma unroll
    for (int mf = 0; mf < 4; mf++) {
        #pragma unroll
        for (int nf = 0; nf < 4; nf++) {
            int m0 = bm * 128 + wm + mf * 16 + g;
            int n0 = bn * 128 + wn + nf * 8 + tg * 2;
            float2 b2 = *(const float2*)&bias[n0];
            float2 v0 = make_float2(acc[mf][nf][0] + b2.x, acc[mf][nf][1] + b2.y);
            float2 v1 = make_float2(acc[mf][nf][2] + b2.x, acc[mf][nf][3] + b2.y);
            *(float2*)(g_zx + (size_t)m0 * G_ + n0)       = v0;
            *(float2*)(g_zx + (size_t)(m0 + 8) * G_ + n0) = v1;
        }
    }
}

// ============================================================================
// lstm_scan: persistent, R smem-resident (gate-interleaved), fused gate phase,
// one grid barrier per step, 5-MUFU gate math (tanh.approx).
// 128 CTAs: bm 0..3 (64 batches) x bn 0..31 (16 units x 4 gates).
// ============================================================================
#define SC_CHUNK 8192                    // 64 rows x 128B per k-chunk
#define SCAN_SMEM (2 * 65536 + 16384)    // sR 64K + sH 64K + zsm 16K

__global__ void __launch_bounds__(256, 1) lstm_scan()
{
    extern __shared__ char sm[];
    const uint32_t sbase = smem_u32(sm);
    const uint32_t sR = sbase, sH = sbase + 65536;
    float (*zsm)[64] = (float(*)[64])(sm + 2 * 65536);
    const int tid = threadIdx.x, wid = tid >> 5, lane = tid & 31;
    const int bid = blockIdx.x;
    const int bm = bid >> 5;     // 0..3   batch tile (64 rows)
    const int bn = bid & 31;     // 0..31  unit tile (16 units x 4 gates)

    const __half* srcH = g_hhi + (size_t)(bm * 64) * H_;
    const __half* srcR = g_R16 + (size_t)(bn * 64) * H_;

    // ---- load R tile once (64KB) ----
    #pragma unroll
    for (int i = 0; i < 16; i++) {
        int q = i * 256 + tid;
        int c = q >> 9, r = (q >> 3) & 63, u = q & 7;
        int off = r * 128 + u * 16;
        cp_async16(sR + c * SC_CHUNK + (off ^ ((off >> 3) & 0x70)),
                   srcR + (size_t)r * H_ + c * 64 + u * 8);
    }
    cp_commit();

    const int wm = (wid >> 2) * 32;   // 2 M-warps
    const int wn = (wid & 3) * 16;    // 4 N-warps
    const int lr = lane & 15, khalf = (lane >> 4) * 16;
    const int g = lane >> 2, tg = lane & 3;

    for (int t = 0; t < T_; t++) {
        if (t > 0) {
            // ---- bulk h load (64KB), single wait ----
            #pragma unroll
            for (int i = 0; i < 16; i++) {
                int q = i * 256 + tid;
                int c = q >> 9, r = (q >> 3) & 63, u = q & 7;
                int off = r * 128 + u * 16;
                cp_async16(sH + c * SC_CHUNK + (off ^ ((off >> 3) & 0x70)),
                           srcH + (size_t)r * H_ + c * 64 + u * 8);
            }
            cp_commit();
            cp_wait0();
            __syncthreads();

            // ---- gemm: zsm(64x64) = h(64x512) @ Rperm^T ----
            float acc[2][2][4];
            #pragma unroll
            for (int a = 0; a < 2; a++)
                #pragma unroll
                for (int b = 0; b < 2; b++)
                    #pragma unroll
                    for (int r = 0; r < 4; r++) acc[a][b][r] = 0.f;

            #pragma unroll
            for (int c = 0; c < 8; c++) {
                const uint32_t cH = sH + c * SC_CHUNK;
                const uint32_t cR = sR + c * SC_CHUNK;
                #pragma unroll
                for (int kb = 0; kb < 4; kb++) {
                    const int kby = kb * 32 + khalf;
                    uint32_t ah[2][4], bf[4];
                    ldsm4(sw_addr(cH, wm + lr, kby), ah[0]);
                    ldsm4(sw_addr(cH, wm + 16 + lr, kby), ah[1]);
                    ldsm4(sw_addr(cR, wn + lr, kby), bf);
                    #pragma unroll
                    for (int mf = 0; mf < 2; mf++)
                        #pragma unroll
                        for (int nf = 0; nf < 2; nf++)
                            mma16816(acc[mf][nf], ah[mf], bf[nf], bf[nf + 2]);
                }
            }
            // epilogue -> zsm (in-CTA)
            #pragma unroll
            for (int mf = 0; mf < 2; mf++) {
                #pragma unroll
                for (int nf = 0; nf < 2; nf++) {
                    int ml = wm + mf * 16 + g;
                    int nl = wn + nf * 8 + tg * 2;
                    zsm[ml][nl]     = acc[mf][nf][0];
                    zsm[ml][nl + 1] = acc[mf][nf][1];
                    zsm[ml + 8][nl]     = acc[mf][nf][2];
                    zsm[ml + 8][nl + 1] = acc[mf][nf][3];
                }
            }
            __syncthreads();
        }

        // ---- fused gate phase: 1024 cells/CTA, 4/thread, 5 MUFU/cell ----
        #pragma unroll
        for (int p = 0; p < 4; p++) {
            int lin = p * 256 + tid;
            int lb = lin >> 4;          // 0..63 local batch
            int jj = lin & 15;          // 0..15 local unit
            int b = bm * 64 + lb;
            int col = bn * 16 + jj;     // global unit
            size_t zxrow = (size_t)(b * T_ + t) * G_;
            float zi = g_zx[zxrow + col];
            float zf = g_zx[zxrow + H_ + col];
            float zg = g_zx[zxrow + 2 * H_ + col];
            float zo = g_zx[zxrow + 3 * H_ + col];
            float cp = 0.0f;
            if (t > 0) {
                zi += zsm[lb][jj];
                zf += zsm[lb][16 + jj];
                zg += zsm[lb][32 + jj];
                zo += zsm[lb][48 + jj];
                cp = g_c[b * H_ + col];
            }
            float ig = sigmoid_fast(zi);
            float fg = sigmoid_fast(zf);
            float gg = tanh_fast(zg);
            float og = sigmoid_fast(zo);
            float cn = fg * cp + ig * gg;
            float hn = og * tanh_fast(cn);
            int ci = b * H_ + col;
            g_c[ci] = cn;
            g_h[ci] = hn;
            g_hhi[ci] = __float2half_rn(hn);
        }
        if (t + 1 < T_) grid_barrier();   // h visible before next step's h load
    }
}

// ============================================================================
// head: y = leaky_relu(hT @ w1 + b1); out = softmax(y @ w2 + b2)
// ============================================================================
__global__ void __launch_bounds__(128) head_kernel(
    const float* __restrict__ w1, const float* __restrict__ b1,
    const float* __restrict__ w2, const float* __restrict__ b2,
    float* __restrict__ out)
{
    __shared__ float hs[H_];
    __shared__ float red0[4], red1[4];
    int b = blockIdx.x;
    int tid = threadIdx.x;

    const float* hrow = g_h + (size_t)b * H_;
    *(float4*)&hs[tid * 4] = *(const float4*)&hrow[tid * 4];
    __syncthreads();

    float a0 = 0.f, a1 = 0.f, a2 = 0.f, a3 = 0.f;
    #pragma unroll 4
    for (int k = 0; k < H_; k += 4) {
        a0 += hs[k]     * w1[(size_t)k * 128 + tid];
        a1 += hs[k + 1] * w1[(size_t)(k + 1) * 128 + tid];
        a2 += hs[k + 2] * w1[(size_t)(k + 2) * 128 + tid];
        a3 += hs[k + 3] * w1[(size_t)(k + 3) * 128 + tid];
    }
    float y = a0 + a1 + a2 + a3 + b1[tid];
    y = (y > 0.f) ? y : 0.2f * y;

    float p0 = y * w2[tid * 2];
    float p1 = y * w2[tid * 2 + 1];
    #pragma unroll
    for (int off = 16; off; off >>= 1) {
        p0 += __shfl_xor_sync(0xffffffffu, p0, off);
        p1 += __shfl_xor_sync(0xffffffffu, p1, off);
    }
    int w = tid >> 5;
    if ((tid & 31) == 0) { red0[w] = p0; red1[w] = p1; }
    __syncthreads();
    if (tid == 0) {
        float l0 = red0[0] + red0[1] + red0[2] + red0[3] + b2[0];
        float l1 = red1[0] + red1[1] + red1[2] + red1[3] + b2[1];
        float m = fmaxf(l0, l1);
        float e0 = expf(l0 - m), e1 = expf(l1 - m);
        float s = e0 + e1;
        out[b * 2]     = e0 / s;
        out[b * 2 + 1] = e1 / s;
    }
}

// ============================================================================
extern "C" void kernel_launch(void* const* d_in, const int* in_sizes, int n_in,
                              void* d_out, int out_size)
{
    const float* x    = (const float*)d_in[0];
    const float* W    = (const float*)d_in[1];
    const float* R    = (const float*)d_in[2];
    const float* bias = (const float*)d_in[3];
    const float* w1   = (const float*)d_in[4];
    const float* b1   = (const float*)d_in[5];
    const float* w2   = (const float*)d_in[6];
    const float* b2   = (const float*)d_in[7];
    float* out = (float*)d_out;

    static int configured = 0;
    if (!configured) {
        cudaFuncSetAttribute(gemm_zx_mma,
            cudaFuncAttributeMaxDynamicSharedMemorySize, GEMM_SMEM);
        cudaFuncSetAttribute(lstm_scan,
            cudaFuncAttributeMaxDynamicSharedMemorySize, SCAN_SMEM);
        configured = 1;
    }

    // slots: harness(1,2) prep_R(3) prep_ab(4) gemm_zx(5) lstm_scan(6) -> ncu on scan
    prep_R<<<dim3(G_ / 32, H_ / 32), dim3(32, 8)>>>(R);
    prep_ab<<<PREPA_BLOCKS + PREPB_BLOCKS, 256>>>(x, W);
    gemm_zx_mma<<<dim3(G_ / 128, M_ / 128), 256, GEMM_SMEM>>>(bias);
    lstm_scan<<<NCTAS_SCAN, 256, SCAN_SMEM>>>();
    head_kernel<<<B_, 128>>>(w1, b1, w2, b2, out);
}